// round 1
// baseline (speedup 1.0000x reference)
#include <cuda_runtime.h>
#include <math.h>

#define B_ 4
#define L_ 2048
#define D_ 1024
#define H_ 16
#define DK_ 64
#define NEGBIG (-1e30f)

// Scratch (device globals — no allocation allowed in kernel_launch)
__device__ float g_qh[B_*H_*L_*DK_];       // 33.5 MB  [b,h,s,k]
__device__ float g_kh[B_*H_*L_*DK_];       // 33.5 MB
__device__ float g_vh[B_*H_*L_*DK_];       // 33.5 MB
__device__ float g_mo[B_*L_*D_];           // 33.5 MB  [b,q,h*64+j]
__device__ unsigned g_mask[B_*L_*(L_/32)]; // 2 MB bit-packed mask

// ---------------------------------------------------------------------------
// Mask bit-pack: 67 MB int32 -> 2 MB bits (1 = keep)
// ---------------------------------------------------------------------------
__global__ void pack_mask_kernel(const int* __restrict__ mask) {
    int idx = blockIdx.x * blockDim.x + threadIdx.x;
    int v = mask[idx];
    unsigned bits = __ballot_sync(0xffffffffu, v != 0);
    if ((threadIdx.x & 31) == 0) g_mask[idx >> 5] = bits;
}

// ---------------------------------------------------------------------------
// Tiled SGEMM: C[M=8192, N=1024] = A[8192,1024] * W  (+bias)
// mode 0: W is head-wise [H, D, 64] (W[d, h*64+kk] = W[h*D*64 + d*64 + kk]),
//         scatter C into g_qh/g_kh/g_vh ("which") as [b,h,s,kk]
// mode 1: A = g_mo (internal), W row-major [1024,1024], C = Cout + bias
// BM=BN=128, BK=16, 256 threads, 8x8 microtile (split 4+4 for bank-friendly LDS.128)
// ---------------------------------------------------------------------------
__global__ __launch_bounds__(256) void gemm_kernel(
    const float* __restrict__ A,
    const float* __restrict__ W,
    const float* __restrict__ bias,
    float* __restrict__ Cout,
    int mode, int which)
{
    __shared__ float As[16][132];   // [k][m], padded: store-conflict-free
    __shared__ float Bs[16][128];   // [k][n]
    const int tid = threadIdx.x;
    const int tx = tid & 15;
    const int ty = tid >> 4;
    const int m0 = blockIdx.y * 128;
    const int n0 = blockIdx.x * 128;

    const float* Ap = (mode == 0) ? A : g_mo;

    float acc[8][8];
    #pragma unroll
    for (int i = 0; i < 8; i++)
        #pragma unroll
        for (int j = 0; j < 8; j++) acc[i][j] = 0.f;

    for (int k0 = 0; k0 < D_; k0 += 16) {
        // A tile: 128 rows x 16 k
        #pragma unroll
        for (int i = 0; i < 2; i++) {
            int f = i * 256 + tid;
            int row = f >> 2;
            int kc = (f & 3) * 4;
            float4 a = *(const float4*)(Ap + (size_t)(m0 + row) * D_ + k0 + kc);
            As[kc + 0][row] = a.x;
            As[kc + 1][row] = a.y;
            As[kc + 2][row] = a.z;
            As[kc + 3][row] = a.w;
        }
        // B tile: 16 k x 128 n
        #pragma unroll
        for (int i = 0; i < 2; i++) {
            int f = i * 256 + tid;
            int kk = f >> 5;
            int nc = (f & 31) * 4;
            const float* src;
            if (mode == 0) {
                int n = n0 + nc;
                src = W + (size_t)(n >> 6) * (D_ * DK_) + (size_t)(k0 + kk) * DK_ + (n & 63);
            } else {
                src = W + (size_t)(k0 + kk) * D_ + (n0 + nc);
            }
            *(float4*)&Bs[kk][nc] = *(const float4*)src;
        }
        __syncthreads();

        #pragma unroll
        for (int k = 0; k < 16; k++) {
            float4 a0 = *(const float4*)&As[k][ty * 4];
            float4 a1 = *(const float4*)&As[k][64 + ty * 4];
            float4 b0 = *(const float4*)&Bs[k][tx * 4];
            float4 b1 = *(const float4*)&Bs[k][64 + tx * 4];
            float ar[8] = {a0.x, a0.y, a0.z, a0.w, a1.x, a1.y, a1.z, a1.w};
            float br[8] = {b0.x, b0.y, b0.z, b0.w, b1.x, b1.y, b1.z, b1.w};
            #pragma unroll
            for (int i = 0; i < 8; i++)
                #pragma unroll
                for (int j = 0; j < 8; j++)
                    acc[i][j] = fmaf(ar[i], br[j], acc[i][j]);
        }
        __syncthreads();
    }

    if (mode == 0) {
        float* out = (which == 0) ? g_qh : (which == 1) ? g_kh : g_vh;
        #pragma unroll
        for (int i = 0; i < 8; i++) {
            int m = m0 + ((i < 4) ? (ty * 4 + i) : (64 + ty * 4 + (i - 4)));
            int b = m >> 11;
            int s = m & (L_ - 1);
            #pragma unroll
            for (int j = 0; j < 8; j++) {
                int n = n0 + ((j < 4) ? (tx * 4 + j) : (64 + tx * 4 + (j - 4)));
                int h = n >> 6;
                int kk = n & 63;
                out[((size_t)(b * H_ + h) * L_ + s) * DK_ + kk] = acc[i][j];
            }
        }
    } else {
        #pragma unroll
        for (int i = 0; i < 8; i++) {
            int m = m0 + ((i < 4) ? (ty * 4 + i) : (64 + ty * 4 + (i - 4)));
            #pragma unroll
            for (int j = 0; j < 8; j++) {
                int n = n0 + ((j < 4) ? (tx * 4 + j) : (64 + tx * 4 + (j - 4)));
                Cout[(size_t)m * D_ + n] = acc[i][j] + bias[n];
            }
        }
    }
}

// ---------------------------------------------------------------------------
// Flash attention (fp32 SIMT). Block = (b, h, q-tile of 64). 256 threads:
// 4 threads per query row (u = tid&3), online softmax, P staged via smem.
// C-tile = 32.  j-columns per thread interleaved (u*4 + 16*jq) for
// conflict-free float4 LDS on V; c interleaved (4*cc+u) likewise on K.
// ---------------------------------------------------------------------------
__global__ __launch_bounds__(256) void attn_kernel() {
    __shared__ float Qs[64][68];
    __shared__ float Ks[32][68];
    __shared__ float Vs[32][68];
    __shared__ float Ps[64][36];

    const int tid = threadIdx.x;
    const int r = tid >> 2;     // query row within tile
    const int u = tid & 3;      // sub-row worker
    const int q0 = blockIdx.x * 64;
    const int h = blockIdx.y;
    const int b = blockIdx.z;

    const float* qbase  = g_qh + ((size_t)(b * H_ + h) * L_ + q0) * DK_;
    const float* kbase0 = g_kh + (size_t)(b * H_ + h) * L_ * DK_;
    const float* vbase0 = g_vh + (size_t)(b * H_ + h) * L_ * DK_;
    const unsigned* mrow = g_mask + (size_t)(b * L_ + q0 + r) * (L_ / 32);

    // Load Q tile (64x64)
    #pragma unroll
    for (int i = 0; i < 4; i++) {
        int f = i * 256 + tid;
        int row = f >> 4;
        int kc = (f & 15) * 4;
        *(float4*)&Qs[row][kc] = *(const float4*)(qbase + row * DK_ + kc);
    }

    float o[16];
    #pragma unroll
    for (int i = 0; i < 16; i++) o[i] = 0.f;
    float rmax = -INFINITY;
    float rsum = 0.f;

    __syncthreads();

    for (int c0 = 0; c0 < L_; c0 += 32) {
        // Load K/V tiles (32x64 each)
        #pragma unroll
        for (int i = 0; i < 2; i++) {
            int f = i * 256 + tid;
            int row = f >> 4;
            int kc = (f & 15) * 4;
            *(float4*)&Ks[row][kc] = *(const float4*)(kbase0 + (size_t)(c0 + row) * DK_ + kc);
            *(float4*)&Vs[row][kc] = *(const float4*)(vbase0 + (size_t)(c0 + row) * DK_ + kc);
        }
        __syncthreads();

        // S = Q K^T for this thread's 8 columns (c = 4*cc + u)
        float s[8];
        #pragma unroll
        for (int cc = 0; cc < 8; cc++) s[cc] = 0.f;
        #pragma unroll
        for (int kq = 0; kq < 16; kq++) {
            float4 qv = *(const float4*)&Qs[r][kq * 4];
            #pragma unroll
            for (int cc = 0; cc < 8; cc++) {
                float4 kv = *(const float4*)&Ks[cc * 4 + u][kq * 4];
                s[cc] += qv.x * kv.x + qv.y * kv.y + qv.z * kv.z + qv.w * kv.w;
            }
        }
        // scale + mask (reference: logits/sqrt(64) + (1-m)*NEG)
        unsigned w = mrow[c0 >> 5];
        #pragma unroll
        for (int cc = 0; cc < 8; cc++) {
            float mk = ((w >> (cc * 4 + u)) & 1u) ? 0.f : NEGBIG;
            s[cc] = s[cc] * 0.125f + mk;
        }

        // online softmax: row max over 4 workers
        float tmax = s[0];
        #pragma unroll
        for (int cc = 1; cc < 8; cc++) tmax = fmaxf(tmax, s[cc]);
        tmax = fmaxf(tmax, __shfl_xor_sync(0xffffffffu, tmax, 1));
        tmax = fmaxf(tmax, __shfl_xor_sync(0xffffffffu, tmax, 2));
        float nm = fmaxf(rmax, tmax);
        float corr = __expf(rmax - nm);
        rsum *= corr;
        #pragma unroll
        for (int i = 0; i < 16; i++) o[i] *= corr;

        float ps = 0.f;
        #pragma unroll
        for (int cc = 0; cc < 8; cc++) {
            float p = __expf(s[cc] - nm);
            Ps[r][cc * 4 + u] = p;
            ps += p;
        }
        ps += __shfl_xor_sync(0xffffffffu, ps, 1);
        ps += __shfl_xor_sync(0xffffffffu, ps, 2);
        rsum += ps;
        rmax = nm;
        __syncthreads();  // Ps ready

        // O += P * V   (thread's j columns: j = jq*16 + u*4 + 0..3)
        #pragma unroll
        for (int c = 0; c < 32; c++) {
            float p = Ps[r][c];
            #pragma unroll
            for (int jq = 0; jq < 4; jq++) {
                float4 vv = *(const float4*)&Vs[c][jq * 16 + u * 4];
                o[jq * 4 + 0] = fmaf(p, vv.x, o[jq * 4 + 0]);
                o[jq * 4 + 1] = fmaf(p, vv.y, o[jq * 4 + 1]);
                o[jq * 4 + 2] = fmaf(p, vv.z, o[jq * 4 + 2]);
                o[jq * 4 + 3] = fmaf(p, vv.w, o[jq * 4 + 3]);
            }
        }
        __syncthreads();  // safe to overwrite Ks/Vs/Ps next iter
    }

    float inv = 1.f / rsum;
    float* outp = g_mo + (size_t)(b * L_ + q0 + r) * D_ + h * DK_;
    #pragma unroll
    for (int jq = 0; jq < 4; jq++) {
        float4 val;
        val.x = o[jq * 4 + 0] * inv;
        val.y = o[jq * 4 + 1] * inv;
        val.z = o[jq * 4 + 2] * inv;
        val.w = o[jq * 4 + 3] * inv;
        *(float4*)(outp + jq * 16 + u * 4) = val;
    }
}

// ---------------------------------------------------------------------------
extern "C" void kernel_launch(void* const* d_in, const int* in_sizes, int n_in,
                              void* d_out, int out_size) {
    const float* q   = (const float*)d_in[0];
    const float* k   = (const float*)d_in[1];
    const float* v   = (const float*)d_in[2];
    const int*   msk = (const int*)d_in[3];
    const float* Wq  = (const float*)d_in[4];
    const float* Wk  = (const float*)d_in[5];
    const float* Wv  = (const float*)d_in[6];
    const float* Wo  = (const float*)d_in[7];
    const float* bo  = (const float*)d_in[8];
    float* out = (float*)d_out;

    pack_mask_kernel<<<(B_ * L_ * L_) / 256, 256>>>(msk);

    dim3 gg(D_ / 128, (B_ * L_) / 128);   // (8, 64)
    gemm_kernel<<<gg, 256>>>(q, Wq, nullptr, nullptr, 0, 0);
    gemm_kernel<<<gg, 256>>>(k, Wk, nullptr, nullptr, 0, 1);
    gemm_kernel<<<gg, 256>>>(v, Wv, nullptr, nullptr, 0, 2);

    attn_kernel<<<dim3(L_ / 64, H_, B_), 256>>>();

    gemm_kernel<<<gg, 256>>>(nullptr, Wo, bo, out, 1, 0);
}

// round 2
// speedup vs baseline: 1.0009x; 1.0009x over previous
#include <cuda_runtime.h>
#include <math.h>

#define B_ 4
#define L_ 2048
#define D_ 1024
#define H_ 16
#define DK_ 64
#define NEGBIG (-1e30f)

// Scratch (device globals — no allocation allowed in kernel_launch)
__device__ float g_qh[B_*H_*L_*DK_];       // 33.5 MB  [b,h,s,k]
__device__ float g_kh[B_*H_*L_*DK_];       // 33.5 MB
__device__ float g_vh[B_*H_*L_*DK_];       // 33.5 MB
__device__ float g_mo[B_*L_*D_];           // 33.5 MB  [b,q,h*64+j]
__device__ unsigned g_mask[B_*L_*(L_/32)]; // 2 MB bit-packed mask

// ---------------------------------------------------------------------------
// Mask bit-pack: 67 MB int32 -> 2 MB bits (1 = keep)
// ---------------------------------------------------------------------------
__global__ void pack_mask_kernel(const int* __restrict__ mask) {
    int idx = blockIdx.x * blockDim.x + threadIdx.x;
    int v = mask[idx];
    unsigned bits = __ballot_sync(0xffffffffu, v != 0);
    if ((threadIdx.x & 31) == 0) g_mask[idx >> 5] = bits;
}

// ---------------------------------------------------------------------------
// Tiled SGEMM: C[M=8192, N=1024] = A[8192,1024] * W  (+bias)
// mode 0: W is head-wise [H, D, 64] (W[d, h*64+kk] = W[h*D*64 + d*64 + kk]),
//         scatter C into g_qh/g_kh/g_vh ("which") as [b,h,s,kk]
// mode 1: A = g_mo (internal), W row-major [1024,1024], C = Cout + bias
// BM=BN=128, BK=16, 256 threads, 8x8 microtile (split 4+4 for bank-friendly LDS.128)
// ---------------------------------------------------------------------------
__global__ __launch_bounds__(256) void gemm_kernel(
    const float* __restrict__ A,
    const float* __restrict__ W,
    const float* __restrict__ bias,
    float* __restrict__ Cout,
    int mode, int which)
{
    __shared__ float As[16][132];   // [k][m], padded: store-conflict-free
    __shared__ float Bs[16][128];   // [k][n]
    const int tid = threadIdx.x;
    const int tx = tid & 15;
    const int ty = tid >> 4;
    const int m0 = blockIdx.y * 128;
    const int n0 = blockIdx.x * 128;

    const float* Ap = (mode == 0) ? A : g_mo;

    float acc[8][8];
    #pragma unroll
    for (int i = 0; i < 8; i++)
        #pragma unroll
        for (int j = 0; j < 8; j++) acc[i][j] = 0.f;

    for (int k0 = 0; k0 < D_; k0 += 16) {
        // A tile: 128 rows x 16 k
        #pragma unroll
        for (int i = 0; i < 2; i++) {
            int f = i * 256 + tid;
            int row = f >> 2;
            int kc = (f & 3) * 4;
            float4 a = *(const float4*)(Ap + (size_t)(m0 + row) * D_ + k0 + kc);
            As[kc + 0][row] = a.x;
            As[kc + 1][row] = a.y;
            As[kc + 2][row] = a.z;
            As[kc + 3][row] = a.w;
        }
        // B tile: 16 k x 128 n
        #pragma unroll
        for (int i = 0; i < 2; i++) {
            int f = i * 256 + tid;
            int kk = f >> 5;
            int nc = (f & 31) * 4;
            const float* src;
            if (mode == 0) {
                int n = n0 + nc;
                src = W + (size_t)(n >> 6) * (D_ * DK_) + (size_t)(k0 + kk) * DK_ + (n & 63);
            } else {
                src = W + (size_t)(k0 + kk) * D_ + (n0 + nc);
            }
            *(float4*)&Bs[kk][nc] = *(const float4*)src;
        }
        __syncthreads();

        #pragma unroll
        for (int k = 0; k < 16; k++) {
            float4 a0 = *(const float4*)&As[k][ty * 4];
            float4 a1 = *(const float4*)&As[k][64 + ty * 4];
            float4 b0 = *(const float4*)&Bs[k][tx * 4];
            float4 b1 = *(const float4*)&Bs[k][64 + tx * 4];
            float ar[8] = {a0.x, a0.y, a0.z, a0.w, a1.x, a1.y, a1.z, a1.w};
            float br[8] = {b0.x, b0.y, b0.z, b0.w, b1.x, b1.y, b1.z, b1.w};
            #pragma unroll
            for (int i = 0; i < 8; i++)
                #pragma unroll
                for (int j = 0; j < 8; j++)
                    acc[i][j] = fmaf(ar[i], br[j], acc[i][j]);
        }
        __syncthreads();
    }

    if (mode == 0) {
        float* out = (which == 0) ? g_qh : (which == 1) ? g_kh : g_vh;
        #pragma unroll
        for (int i = 0; i < 8; i++) {
            int m = m0 + ((i < 4) ? (ty * 4 + i) : (64 + ty * 4 + (i - 4)));
            int b = m >> 11;
            int s = m & (L_ - 1);
            #pragma unroll
            for (int j = 0; j < 8; j++) {
                int n = n0 + ((j < 4) ? (tx * 4 + j) : (64 + tx * 4 + (j - 4)));
                int h = n >> 6;
                int kk = n & 63;
                out[((size_t)(b * H_ + h) * L_ + s) * DK_ + kk] = acc[i][j];
            }
        }
    } else {
        #pragma unroll
        for (int i = 0; i < 8; i++) {
            int m = m0 + ((i < 4) ? (ty * 4 + i) : (64 + ty * 4 + (i - 4)));
            #pragma unroll
            for (int j = 0; j < 8; j++) {
                int n = n0 + ((j < 4) ? (tx * 4 + j) : (64 + tx * 4 + (j - 4)));
                Cout[(size_t)m * D_ + n] = acc[i][j] + bias[n];
            }
        }
    }
}

// ---------------------------------------------------------------------------
// Flash attention (fp32 SIMT). Block = (b, h, q-tile of 64). 256 threads:
// 4 threads per query row (u = tid&3), online softmax, P staged via smem.
// C-tile = 32.  j-columns per thread interleaved (u*4 + 16*jq) for
// conflict-free float4 LDS on V; c interleaved (4*cc+u) likewise on K.
// ---------------------------------------------------------------------------
__global__ __launch_bounds__(256) void attn_kernel() {
    __shared__ float Qs[64][68];
    __shared__ float Ks[32][68];
    __shared__ float Vs[32][68];
    __shared__ float Ps[64][36];

    const int tid = threadIdx.x;
    const int r = tid >> 2;     // query row within tile
    const int u = tid & 3;      // sub-row worker
    const int q0 = blockIdx.x * 64;
    const int h = blockIdx.y;
    const int b = blockIdx.z;

    const float* qbase  = g_qh + ((size_t)(b * H_ + h) * L_ + q0) * DK_;
    const float* kbase0 = g_kh + (size_t)(b * H_ + h) * L_ * DK_;
    const float* vbase0 = g_vh + (size_t)(b * H_ + h) * L_ * DK_;
    const unsigned* mrow = g_mask + (size_t)(b * L_ + q0 + r) * (L_ / 32);

    // Load Q tile (64x64)
    #pragma unroll
    for (int i = 0; i < 4; i++) {
        int f = i * 256 + tid;
        int row = f >> 4;
        int kc = (f & 15) * 4;
        *(float4*)&Qs[row][kc] = *(const float4*)(qbase + row * DK_ + kc);
    }

    float o[16];
    #pragma unroll
    for (int i = 0; i < 16; i++) o[i] = 0.f;
    float rmax = -INFINITY;
    float rsum = 0.f;

    __syncthreads();

    for (int c0 = 0; c0 < L_; c0 += 32) {
        // Load K/V tiles (32x64 each)
        #pragma unroll
        for (int i = 0; i < 2; i++) {
            int f = i * 256 + tid;
            int row = f >> 4;
            int kc = (f & 15) * 4;
            *(float4*)&Ks[row][kc] = *(const float4*)(kbase0 + (size_t)(c0 + row) * DK_ + kc);
            *(float4*)&Vs[row][kc] = *(const float4*)(vbase0 + (size_t)(c0 + row) * DK_ + kc);
        }
        __syncthreads();

        // S = Q K^T for this thread's 8 columns (c = 4*cc + u)
        float s[8];
        #pragma unroll
        for (int cc = 0; cc < 8; cc++) s[cc] = 0.f;
        #pragma unroll
        for (int kq = 0; kq < 16; kq++) {
            float4 qv = *(const float4*)&Qs[r][kq * 4];
            #pragma unroll
            for (int cc = 0; cc < 8; cc++) {
                float4 kv = *(const float4*)&Ks[cc * 4 + u][kq * 4];
                s[cc] += qv.x * kv.x + qv.y * kv.y + qv.z * kv.z + qv.w * kv.w;
            }
        }
        // scale + mask (reference: logits/sqrt(64) + (1-m)*NEG)
        unsigned w = mrow[c0 >> 5];
        #pragma unroll
        for (int cc = 0; cc < 8; cc++) {
            float mk = ((w >> (cc * 4 + u)) & 1u) ? 0.f : NEGBIG;
            s[cc] = s[cc] * 0.125f + mk;
        }

        // online softmax: row max over 4 workers
        float tmax = s[0];
        #pragma unroll
        for (int cc = 1; cc < 8; cc++) tmax = fmaxf(tmax, s[cc]);
        tmax = fmaxf(tmax, __shfl_xor_sync(0xffffffffu, tmax, 1));
        tmax = fmaxf(tmax, __shfl_xor_sync(0xffffffffu, tmax, 2));
        float nm = fmaxf(rmax, tmax);
        float corr = __expf(rmax - nm);
        rsum *= corr;
        #pragma unroll
        for (int i = 0; i < 16; i++) o[i] *= corr;

        float ps = 0.f;
        #pragma unroll
        for (int cc = 0; cc < 8; cc++) {
            float p = __expf(s[cc] - nm);
            Ps[r][cc * 4 + u] = p;
            ps += p;
        }
        ps += __shfl_xor_sync(0xffffffffu, ps, 1);
        ps += __shfl_xor_sync(0xffffffffu, ps, 2);
        rsum += ps;
        rmax = nm;
        __syncthreads();  // Ps ready

        // O += P * V   (thread's j columns: j = jq*16 + u*4 + 0..3)
        #pragma unroll
        for (int c = 0; c < 32; c++) {
            float p = Ps[r][c];
            #pragma unroll
            for (int jq = 0; jq < 4; jq++) {
                float4 vv = *(const float4*)&Vs[c][jq * 16 + u * 4];
                o[jq * 4 + 0] = fmaf(p, vv.x, o[jq * 4 + 0]);
                o[jq * 4 + 1] = fmaf(p, vv.y, o[jq * 4 + 1]);
                o[jq * 4 + 2] = fmaf(p, vv.z, o[jq * 4 + 2]);
                o[jq * 4 + 3] = fmaf(p, vv.w, o[jq * 4 + 3]);
            }
        }
        __syncthreads();  // safe to overwrite Ks/Vs/Ps next iter
    }

    float inv = 1.f / rsum;
    float* outp = g_mo + (size_t)(b * L_ + q0 + r) * D_ + h * DK_;
    #pragma unroll
    for (int jq = 0; jq < 4; jq++) {
        float4 val;
        val.x = o[jq * 4 + 0] * inv;
        val.y = o[jq * 4 + 1] * inv;
        val.z = o[jq * 4 + 2] * inv;
        val.w = o[jq * 4 + 3] * inv;
        *(float4*)(outp + jq * 16 + u * 4) = val;
    }
}

// ---------------------------------------------------------------------------
extern "C" void kernel_launch(void* const* d_in, const int* in_sizes, int n_in,
                              void* d_out, int out_size) {
    const float* q   = (const float*)d_in[0];
    const float* k   = (const float*)d_in[1];
    const float* v   = (const float*)d_in[2];
    const int*   msk = (const int*)d_in[3];
    const float* Wq  = (const float*)d_in[4];
    const float* Wk  = (const float*)d_in[5];
    const float* Wv  = (const float*)d_in[6];
    const float* Wo  = (const float*)d_in[7];
    const float* bo  = (const float*)d_in[8];
    float* out = (float*)d_out;

    pack_mask_kernel<<<(B_ * L_ * L_) / 256, 256>>>(msk);

    dim3 gg(D_ / 128, (B_ * L_) / 128);   // (8, 64)
    gemm_kernel<<<gg, 256>>>(q, Wq, nullptr, nullptr, 0, 0);
    gemm_kernel<<<gg, 256>>>(k, Wk, nullptr, nullptr, 0, 1);
    gemm_kernel<<<gg, 256>>>(v, Wv, nullptr, nullptr, 0, 2);

    attn_kernel<<<dim3(L_ / 64, H_, B_), 256>>>();

    gemm_kernel<<<gg, 256>>>(nullptr, Wo, bo, out, 1, 0);
}

// round 4
// speedup vs baseline: 2.0994x; 2.0975x over previous
#include <cuda_runtime.h>
#include <cuda_bf16.h>
#include <math.h>
#include <cstdint>

#define B_ 4
#define L_ 2048
#define D_ 1024
#define H_ 16
#define DK_ 64

// ---------------------------------------------------------------------------
// Device scratch
// ---------------------------------------------------------------------------
__device__ float g_mo[B_*L_*D_];             // 33.5 MB  attention out [b,q,h*64+j]
__device__ unsigned g_mask[B_*L_*(L_/32)];   // 2 MB bit-packed mask
// bf16 hi/lo split operands produced by projection GEMMs, layout [b,h,s,k]
__device__ __nv_bfloat16 g_q_hi[B_*H_*L_*DK_];
__device__ __nv_bfloat16 g_q_lo[B_*H_*L_*DK_];
__device__ __nv_bfloat16 g_k_hi[B_*H_*L_*DK_];
__device__ __nv_bfloat16 g_k_lo[B_*H_*L_*DK_];
__device__ __nv_bfloat16 g_v_hi[B_*H_*L_*DK_];
__device__ __nv_bfloat16 g_v_lo[B_*H_*L_*DK_];

// ---------------------------------------------------------------------------
// sm_80-compatible tensor-core primitives (work on plain sm_100 target)
// ---------------------------------------------------------------------------
__device__ __forceinline__ uint32_t smem_to_u32(const void* p) {
    uint32_t a;
    asm("{ .reg .u64 t; cvta.to.shared.u64 t, %1; cvt.u32.u64 %0, t; }" : "=r"(a) : "l"(p));
    return a;
}
__device__ __forceinline__ void ldsm4(uint32_t d[4], uint32_t addr) {
    asm volatile("ldmatrix.sync.aligned.m8n8.x4.shared.b16 {%0,%1,%2,%3}, [%4];"
        : "=r"(d[0]), "=r"(d[1]), "=r"(d[2]), "=r"(d[3]) : "r"(addr));
}
__device__ __forceinline__ void ldsm4t(uint32_t d[4], uint32_t addr) {
    asm volatile("ldmatrix.sync.aligned.m8n8.x4.trans.shared.b16 {%0,%1,%2,%3}, [%4];"
        : "=r"(d[0]), "=r"(d[1]), "=r"(d[2]), "=r"(d[3]) : "r"(addr));
}
__device__ __forceinline__ void mma_bf16(float c[4], const uint32_t a[4], const uint32_t b[2]) {
    asm volatile("mma.sync.aligned.m16n8k16.row.col.f32.bf16.bf16.f32 "
        "{%0,%1,%2,%3}, {%4,%5,%6,%7}, {%8,%9}, {%0,%1,%2,%3};"
        : "+f"(c[0]), "+f"(c[1]), "+f"(c[2]), "+f"(c[3])
        : "r"(a[0]), "r"(a[1]), "r"(a[2]), "r"(a[3]), "r"(b[0]), "r"(b[1]));
}
__device__ __forceinline__ uint32_t pack_bf16(float x, float y) {
    __nv_bfloat162 t = __floats2bfloat162_rn(x, y);
    return *reinterpret_cast<uint32_t*>(&t);
}

// ---------------------------------------------------------------------------
// Mask bit-pack: 67 MB int32 -> 2 MB bits (1 = keep)
// ---------------------------------------------------------------------------
__global__ void pack_mask_kernel(const int* __restrict__ mask) {
    int idx = blockIdx.x * blockDim.x + threadIdx.x;
    int v = mask[idx];
    unsigned bits = __ballot_sync(0xffffffffu, v != 0);
    if ((threadIdx.x & 31) == 0) g_mask[idx >> 5] = bits;
}

// ---------------------------------------------------------------------------
// Tiled SGEMM. mode 0: projections -> bf16 hi/lo [b,h,s,k]
// mode 1: out proj from g_mo -> d_out fp32 + bias
// ---------------------------------------------------------------------------
__global__ __launch_bounds__(256) void gemm_kernel(
    const float* __restrict__ A,
    const float* __restrict__ W,
    const float* __restrict__ bias,
    float* __restrict__ Cout,
    int mode, int which)
{
    __shared__ float As[16][132];
    __shared__ float Bs[16][128];
    const int tid = threadIdx.x;
    const int tx = tid & 15;
    const int ty = tid >> 4;
    const int m0 = blockIdx.y * 128;
    const int n0 = blockIdx.x * 128;

    const float* Ap = (mode == 0) ? A : g_mo;

    float acc[8][8];
    #pragma unroll
    for (int i = 0; i < 8; i++)
        #pragma unroll
        for (int j = 0; j < 8; j++) acc[i][j] = 0.f;

    for (int k0 = 0; k0 < D_; k0 += 16) {
        #pragma unroll
        for (int i = 0; i < 2; i++) {
            int f = i * 256 + tid;
            int row = f >> 2;
            int kc = (f & 3) * 4;
            float4 a = *(const float4*)(Ap + (size_t)(m0 + row) * D_ + k0 + kc);
            As[kc + 0][row] = a.x;
            As[kc + 1][row] = a.y;
            As[kc + 2][row] = a.z;
            As[kc + 3][row] = a.w;
        }
        #pragma unroll
        for (int i = 0; i < 2; i++) {
            int f = i * 256 + tid;
            int kk = f >> 5;
            int nc = (f & 31) * 4;
            const float* src;
            if (mode == 0) {
                int n = n0 + nc;
                src = W + (size_t)(n >> 6) * (D_ * DK_) + (size_t)(k0 + kk) * DK_ + (n & 63);
            } else {
                src = W + (size_t)(k0 + kk) * D_ + (n0 + nc);
            }
            *(float4*)&Bs[kk][nc] = *(const float4*)src;
        }
        __syncthreads();

        #pragma unroll
        for (int k = 0; k < 16; k++) {
            float4 a0 = *(const float4*)&As[k][ty * 4];
            float4 a1 = *(const float4*)&As[k][64 + ty * 4];
            float4 b0 = *(const float4*)&Bs[k][tx * 4];
            float4 b1 = *(const float4*)&Bs[k][64 + tx * 4];
            float ar[8] = {a0.x, a0.y, a0.z, a0.w, a1.x, a1.y, a1.z, a1.w};
            float br[8] = {b0.x, b0.y, b0.z, b0.w, b1.x, b1.y, b1.z, b1.w};
            #pragma unroll
            for (int i = 0; i < 8; i++)
                #pragma unroll
                for (int j = 0; j < 8; j++)
                    acc[i][j] = fmaf(ar[i], br[j], acc[i][j]);
        }
        __syncthreads();
    }

    if (mode == 0) {
        __nv_bfloat16* hi_arr = (which == 0) ? g_q_hi : (which == 1) ? g_k_hi : g_v_hi;
        __nv_bfloat16* lo_arr = (which == 0) ? g_q_lo : (which == 1) ? g_k_lo : g_v_lo;
        #pragma unroll
        for (int i = 0; i < 8; i++) {
            int m = m0 + ((i < 4) ? (ty * 4 + i) : (64 + ty * 4 + (i - 4)));
            int b = m >> 11;
            int s = m & (L_ - 1);
            #pragma unroll
            for (int jp = 0; jp < 4; jp++) {
                int j0 = jp * 2;
                int n = n0 + ((j0 < 4) ? (tx * 4 + j0) : (64 + tx * 4 + (j0 - 4)));
                int hh = n >> 6;
                int kk = n & 63;
                float a0 = acc[i][j0], a1 = acc[i][j0 + 1];
                __nv_bfloat16 h0 = __float2bfloat16_rn(a0);
                __nv_bfloat16 h1 = __float2bfloat16_rn(a1);
                float l0 = a0 - __bfloat162float(h0);
                float l1 = a1 - __bfloat162float(h1);
                uint32_t hp = (uint32_t)__bfloat16_as_ushort(h0) |
                              ((uint32_t)__bfloat16_as_ushort(h1) << 16);
                uint32_t lp = (uint32_t)__bfloat16_as_ushort(__float2bfloat16_rn(l0)) |
                              ((uint32_t)__bfloat16_as_ushort(__float2bfloat16_rn(l1)) << 16);
                size_t eidx = (((size_t)(b * H_ + hh) * L_ + s) * DK_ + kk) >> 1;
                ((uint32_t*)hi_arr)[eidx] = hp;
                ((uint32_t*)lo_arr)[eidx] = lp;
            }
        }
    } else {
        #pragma unroll
        for (int i = 0; i < 8; i++) {
            int m = m0 + ((i < 4) ? (ty * 4 + i) : (64 + ty * 4 + (i - 4)));
            #pragma unroll
            for (int j = 0; j < 8; j++) {
                int n = n0 + ((j < 4) ? (tx * 4 + j) : (64 + tx * 4 + (j - 4)));
                Cout[(size_t)m * D_ + n] = acc[i][j] + bias[n];
            }
        }
    }
}

// ---------------------------------------------------------------------------
// Tensor-core flash attention via mma.sync (bf16 hi/lo, 3 products).
// Block: 256 threads (8 warps), QT=128 rows (warp w owns rows 16w..16w+15),
// CT=64 key tile. No-max softmax; O accumulates in fp32 registers.
// Smem (dynamic, 64KB): Qhi/Qlo [128x64 bf16], Khi/Klo/Vhi/Vlo [64x64 bf16],
// all SW128-xor swizzled (chunk16B: ch ^ (row&7)) -> conflict-free ldmatrix.
// ---------------------------------------------------------------------------
#define QT 128
#define CT 64
#define O_QHI 0
#define O_QLO 16384
#define O_KHI 32768
#define O_KLO 40960
#define O_VHI 49152
#define O_VLO 57344
#define ATTN_SMEM 65536

__global__ __launch_bounds__(256, 2) void attn_mma_kernel() {
    extern __shared__ char smem[];
    const uint32_t sb = smem_to_u32(smem);
    const int tid = threadIdx.x;
    const int w = tid >> 5;
    const int L = tid & 31;
    const int q0 = blockIdx.x * QT;
    const int h = blockIdx.y;
    const int b = blockIdx.z;
    const size_t bh = (size_t)(b * H_ + h);

    // ---- stage Q tile (hi+lo) into swizzled smem ----
    {
        const uint4* qh4 = (const uint4*)(g_q_hi + (bh * L_ + q0) * DK_);
        const uint4* ql4 = (const uint4*)(g_q_lo + (bh * L_ + q0) * DK_);
        #pragma unroll
        for (int i = 0; i < 4; i++) {
            int f = i * 256 + tid;
            int r = f >> 3, ch = f & 7;
            uint32_t off = (uint32_t)(r * 128 + ((ch ^ (r & 7)) << 4));
            *(uint4*)(smem + O_QHI + off) = qh4[f];
            *(uint4*)(smem + O_QLO + off) = ql4[f];
        }
    }

    const uint4* kh4 = (const uint4*)(g_k_hi + bh * L_ * DK_);
    const uint4* kl4 = (const uint4*)(g_k_lo + bh * L_ * DK_);
    const uint4* vh4 = (const uint4*)(g_v_hi + bh * L_ * DK_);
    const uint4* vl4 = (const uint4*)(g_v_lo + bh * L_ * DK_);

    // lane-fixed ldmatrix row components
    const int rq = 16 * w + (L & 7) + ((L >> 3) & 1) * 8;    // Q (A frag)
    const int rk_sub = ((L >> 4) & 1) * 8 + (L & 7);         // K rows: +16*tp
    const int rv_sub = ((L >> 3) & 1) * 8 + (L & 7);         // V rows: +16*g
    const int chq_sub = (L >> 4) & 1;                        // Q chunk: +2g
    const int chk_sub = (L >> 3) & 1;                        // K chunk: +2g
    const int chv_sub = (L >> 4) & 1;                        // V chunk: +2tp

    // mask row pointers (rows r1 = 16w + L/4, r2 = r1+8)
    const int r1 = 16 * w + (L >> 2);
    const unsigned* mp1 = g_mask + (size_t)(b * L_ + q0 + r1) * (L_ / 32);
    const unsigned* mp2 = mp1 + 8 * (L_ / 32);

    float o[8][4];
    #pragma unroll
    for (int t = 0; t < 8; t++)
        #pragma unroll
        for (int e = 0; e < 4; e++) o[t][e] = 0.f;
    float rs1 = 0.f, rs2 = 0.f;

    for (int c0 = 0; c0 < L_; c0 += CT) {
        __syncthreads();   // previous tile's ldmatrix reads done
        // ---- stage K/V hi/lo (64x64 bf16 each) ----
        #pragma unroll
        for (int i = 0; i < 2; i++) {
            int f = i * 256 + tid;
            int r = f >> 3, ch = f & 7;
            uint32_t off = (uint32_t)(r * 128 + ((ch ^ (r & 7)) << 4));
            int gi = c0 * 8 + f;
            *(uint4*)(smem + O_KHI + off) = kh4[gi];
            *(uint4*)(smem + O_KLO + off) = kl4[gi];
            *(uint4*)(smem + O_VHI + off) = vh4[gi];
            *(uint4*)(smem + O_VLO + off) = vl4[gi];
        }
        __syncthreads();

        // ---- S = Q K^T ----
        float s[8][4];
        #pragma unroll
        for (int t = 0; t < 8; t++)
            #pragma unroll
            for (int e = 0; e < 4; e++) s[t][e] = 0.f;

        #pragma unroll
        for (int g = 0; g < 4; g++) {
            uint32_t qh[4], ql[4];
            int chq = 2 * g + chq_sub;
            uint32_t qoff = (uint32_t)(rq * 128 + ((chq ^ (rq & 7)) << 4));
            ldsm4(qh, sb + O_QHI + qoff);
            ldsm4(ql, sb + O_QLO + qoff);
            #pragma unroll
            for (int tp = 0; tp < 4; tp++) {
                uint32_t kh[4], kl[4];
                int rk = 16 * tp + rk_sub;
                int chk = 2 * g + chk_sub;
                uint32_t koff = (uint32_t)(rk * 128 + ((chk ^ (rk & 7)) << 4));
                ldsm4(kh, sb + O_KHI + koff);
                ldsm4(kl, sb + O_KLO + koff);
                mma_bf16(s[2 * tp], qh, kh);
                mma_bf16(s[2 * tp], qh, kl);
                mma_bf16(s[2 * tp], ql, kh);
                mma_bf16(s[2 * tp + 1], qh, kh + 2);
                mma_bf16(s[2 * tp + 1], qh, kl + 2);
                mma_bf16(s[2 * tp + 1], ql, kh + 2);
            }
        }

        // ---- softmax (no max subtraction) + pack P into A fragments ----
        uint2 mwa = *(const uint2*)(mp1 + (c0 >> 5));
        uint2 mwb = *(const uint2*)(mp2 + (c0 >> 5));
        uint32_t ahi[4][4], alo[4][4];
        #pragma unroll
        for (int t = 0; t < 8; t++) {
            unsigned wa = (t < 4) ? mwa.x : mwa.y;
            unsigned wb = (t < 4) ? mwb.x : mwb.y;
            int sh = ((t & 3) << 3) + ((L & 3) << 1);
            float p0 = ((wa >> sh) & 1u)       ? __expf(s[t][0] * 0.125f) : 0.f;
            float p1 = ((wa >> (sh + 1)) & 1u) ? __expf(s[t][1] * 0.125f) : 0.f;
            float p2 = ((wb >> sh) & 1u)       ? __expf(s[t][2] * 0.125f) : 0.f;
            float p3 = ((wb >> (sh + 1)) & 1u) ? __expf(s[t][3] * 0.125f) : 0.f;
            rs1 += p0 + p1;
            rs2 += p2 + p3;
            float h0 = __bfloat162float(__float2bfloat16_rn(p0));
            float h1 = __bfloat162float(__float2bfloat16_rn(p1));
            float h2 = __bfloat162float(__float2bfloat16_rn(p2));
            float h3 = __bfloat162float(__float2bfloat16_rn(p3));
            int g = t >> 1, e = (t & 1) * 2;
            ahi[g][e]     = pack_bf16(h0, h1);
            ahi[g][e + 1] = pack_bf16(h2, h3);
            alo[g][e]     = pack_bf16(p0 - h0, p1 - h1);
            alo[g][e + 1] = pack_bf16(p2 - h2, p3 - h3);
        }

        // ---- O += P V  (V via ldmatrix.trans) ----
        #pragma unroll
        for (int g = 0; g < 4; g++) {
            int rv = 16 * g + rv_sub;
            #pragma unroll
            for (int tp = 0; tp < 4; tp++) {
                uint32_t vh[4], vl[4];
                int chv = 2 * tp + chv_sub;
                uint32_t voff = (uint32_t)(rv * 128 + ((chv ^ (rv & 7)) << 4));
                ldsm4t(vh, sb + O_VHI + voff);
                ldsm4t(vl, sb + O_VLO + voff);
                mma_bf16(o[2 * tp], ahi[g], vh);
                mma_bf16(o[2 * tp], ahi[g], vl);
                mma_bf16(o[2 * tp], alo[g], vh);
                mma_bf16(o[2 * tp + 1], ahi[g], vh + 2);
                mma_bf16(o[2 * tp + 1], ahi[g], vl + 2);
                mma_bf16(o[2 * tp + 1], alo[g], vh + 2);
            }
        }
    }

    // ---- normalize + store ----
    rs1 += __shfl_xor_sync(0xffffffffu, rs1, 1);
    rs1 += __shfl_xor_sync(0xffffffffu, rs1, 2);
    rs2 += __shfl_xor_sync(0xffffffffu, rs2, 1);
    rs2 += __shfl_xor_sync(0xffffffffu, rs2, 2);
    float i1 = 1.f / rs1;
    float i2 = 1.f / rs2;

    float* op1 = g_mo + (size_t)(b * L_ + q0 + r1) * D_ + h * DK_;
    float* op2 = op1 + 8 * D_;
    #pragma unroll
    for (int t = 0; t < 8; t++) {
        int j = 8 * t + ((L & 3) << 1);
        float2 v1 = make_float2(o[t][0] * i1, o[t][1] * i1);
        float2 v2 = make_float2(o[t][2] * i2, o[t][3] * i2);
        *(float2*)(op1 + j) = v1;
        *(float2*)(op2 + j) = v2;
    }
}

// ---------------------------------------------------------------------------
extern "C" void kernel_launch(void* const* d_in, const int* in_sizes, int n_in,
                              void* d_out, int out_size) {
    const float* q   = (const float*)d_in[0];
    const float* k   = (const float*)d_in[1];
    const float* v   = (const float*)d_in[2];
    const int*   msk = (const int*)d_in[3];
    const float* Wq  = (const float*)d_in[4];
    const float* Wk  = (const float*)d_in[5];
    const float* Wv  = (const float*)d_in[6];
    const float* Wo  = (const float*)d_in[7];
    const float* bo  = (const float*)d_in[8];
    float* out = (float*)d_out;

    static int attr_done = 0;
    if (!attr_done) {
        cudaFuncSetAttribute(attn_mma_kernel,
                             cudaFuncAttributeMaxDynamicSharedMemorySize, ATTN_SMEM);
        attr_done = 1;
    }

    pack_mask_kernel<<<(B_ * L_ * L_) / 256, 256>>>(msk);

    dim3 gg(D_ / 128, (B_ * L_) / 128);
    gemm_kernel<<<gg, 256>>>(q, Wq, nullptr, nullptr, 0, 0);
    gemm_kernel<<<gg, 256>>>(k, Wk, nullptr, nullptr, 0, 1);
    gemm_kernel<<<gg, 256>>>(v, Wv, nullptr, nullptr, 0, 2);

    attn_mma_kernel<<<dim3(L_ / QT, H_, B_), 256, ATTN_SMEM>>>();

    gemm_kernel<<<gg, 256>>>(nullptr, Wo, bo, out, 1, 0);
}

// round 7
// speedup vs baseline: 4.0223x; 1.9159x over previous
#include <cuda_runtime.h>
#include <cuda_bf16.h>
#include <math.h>
#include <cstdint>

#define B_ 4
#define L_ 2048
#define D_ 1024
#define H_ 16
#define DK_ 64

// ---------------------------------------------------------------------------
// Device scratch
// ---------------------------------------------------------------------------
__device__ float g_mo[B_*L_*D_];             // 33.5 MB  attention out [b,q,h*64+j]
__device__ unsigned g_mask[B_*L_*(L_/32)];   // 2 MB bit-packed mask
// bf16 hi/lo split operands produced by projection GEMMs, layout [b,h,s,k]
__device__ __nv_bfloat16 g_q_hi[B_*H_*L_*DK_];
__device__ __nv_bfloat16 g_q_lo[B_*H_*L_*DK_];
__device__ __nv_bfloat16 g_k_hi[B_*H_*L_*DK_];
__device__ __nv_bfloat16 g_k_lo[B_*H_*L_*DK_];
__device__ __nv_bfloat16 g_v_hi[B_*H_*L_*DK_];
__device__ __nv_bfloat16 g_v_lo[B_*H_*L_*DK_];

// ---------------------------------------------------------------------------
// sm_80-compatible tensor-core primitives (work on plain sm_100 target)
// ---------------------------------------------------------------------------
__device__ __forceinline__ uint32_t smem_to_u32(const void* p) {
    uint32_t a;
    asm("{ .reg .u64 t; cvta.to.shared.u64 t, %1; cvt.u32.u64 %0, t; }" : "=r"(a) : "l"(p));
    return a;
}
__device__ __forceinline__ void ldsm4(uint32_t d[4], uint32_t addr) {
    asm volatile("ldmatrix.sync.aligned.m8n8.x4.shared.b16 {%0,%1,%2,%3}, [%4];"
        : "=r"(d[0]), "=r"(d[1]), "=r"(d[2]), "=r"(d[3]) : "r"(addr));
}
__device__ __forceinline__ void ldsm4t(uint32_t d[4], uint32_t addr) {
    asm volatile("ldmatrix.sync.aligned.m8n8.x4.trans.shared.b16 {%0,%1,%2,%3}, [%4];"
        : "=r"(d[0]), "=r"(d[1]), "=r"(d[2]), "=r"(d[3]) : "r"(addr));
}
__device__ __forceinline__ void mma_bf16(float c[4], const uint32_t a[4], const uint32_t b[2]) {
    asm volatile("mma.sync.aligned.m16n8k16.row.col.f32.bf16.bf16.f32 "
        "{%0,%1,%2,%3}, {%4,%5,%6,%7}, {%8,%9}, {%0,%1,%2,%3};"
        : "+f"(c[0]), "+f"(c[1]), "+f"(c[2]), "+f"(c[3])
        : "r"(a[0]), "r"(a[1]), "r"(a[2]), "r"(a[3]), "r"(b[0]), "r"(b[1]));
}
__device__ __forceinline__ uint32_t pack_bf16(float x, float y) {
    __nv_bfloat162 t = __floats2bfloat162_rn(x, y);
    return *reinterpret_cast<uint32_t*>(&t);
}

// ---------------------------------------------------------------------------
// Mask bit-pack: 67 MB int32 -> 2 MB bits (1 = keep)
// ---------------------------------------------------------------------------
__global__ void pack_mask_kernel(const int* __restrict__ mask) {
    int idx = blockIdx.x * blockDim.x + threadIdx.x;
    int v = mask[idx];
    unsigned bits = __ballot_sync(0xffffffffu, v != 0);
    if ((threadIdx.x & 31) == 0) g_mask[idx >> 5] = bits;
}

// ---------------------------------------------------------------------------
// Tensor-core GEMM (bf16 hi/lo x3): C[8192,1024] = A * W (+bias)
// BM=128 BN=128 BK=64, 256 thr (8 warps: 4m x 2n), warp tile 32x64.
// A staged k-major (ldsm4), W staged [k][n] two 64-col halves (ldsm4t).
// mode 0: A=q/k/v input, W head-wise [H,D,64]; out -> bf16 hi/lo [b,h,s,k]
// mode 1: A=g_mo, W row-major [1024,1024]; out -> Cout fp32 + bias
// ---------------------------------------------------------------------------
#define G_AHI 0
#define G_ALO 16384
#define G_WHI 32768
#define G_WLO 49152
#define GEMM_SMEM 65536

__global__ __launch_bounds__(256, 2) void gemm_tc_kernel(
    const float* __restrict__ A,
    const float* __restrict__ W,
    const float* __restrict__ bias,
    float* __restrict__ Cout,
    int mode, int which)
{
    extern __shared__ char smem[];
    const uint32_t sb = smem_to_u32(smem);
    const int tid = threadIdx.x;
    const int w = tid >> 5;
    const int L = tid & 31;
    const int wm = w >> 1;          // 0..3  (m)
    const int wn = w & 1;           // 0..1  (n half)
    const int m0 = blockIdx.y * 128;
    const int n0 = blockIdx.x * 128;

    const float* Ap = (mode == 0) ? A : g_mo;

    // lane-fixed fragment address components
    const int ra_sub = (L & 7) + ((L >> 3) & 1) * 8;   // A rows (+16*mt +32*wm)
    const int cha_sub = (L >> 4) & 1;                  // A chunk (+2g)
    const int rb_sub = ((L >> 3) & 1) * 8 + (L & 7);   // W rows (+16*g)
    const int chb_sub = (L >> 4) & 1;                  // W chunk (+2tp)

    float acc[2][8][4];
    #pragma unroll
    for (int mt = 0; mt < 2; mt++)
        #pragma unroll
        for (int nt = 0; nt < 8; nt++)
            #pragma unroll
            for (int e = 0; e < 4; e++) acc[mt][nt][e] = 0.f;

    for (int k0 = 0; k0 < D_; k0 += 64) {
        __syncthreads();
        // ---- stage A tile: 128 rows x 64 k fp32 -> bf16 hi/lo swizzled ----
        #pragma unroll
        for (int i = 0; i < 8; i++) {
            int f = i * 256 + tid;
            int r = f >> 4;
            int kc = (f & 15) * 4;
            float4 a = *(const float4*)(Ap + (size_t)(m0 + r) * D_ + k0 + kc);
            float h0 = __bfloat162float(__float2bfloat16_rn(a.x));
            float h1 = __bfloat162float(__float2bfloat16_rn(a.y));
            float h2 = __bfloat162float(__float2bfloat16_rn(a.z));
            float h3 = __bfloat162float(__float2bfloat16_rn(a.w));
            uint2 hp = make_uint2(pack_bf16(h0, h1), pack_bf16(h2, h3));
            uint2 lp = make_uint2(pack_bf16(a.x - h0, a.y - h1),
                                  pack_bf16(a.z - h2, a.w - h3));
            uint32_t off = (uint32_t)(r * 128 + (((kc >> 3) ^ (r & 7)) << 4) + ((kc & 4) << 1));
            *(uint2*)(smem + G_AHI + off) = hp;
            *(uint2*)(smem + G_ALO + off) = lp;
        }
        // ---- stage W tile: 64 k-rows x 128 n fp32 -> [half][k][n] bf16 hi/lo ----
        #pragma unroll
        for (int i = 0; i < 8; i++) {
            int f = i * 256 + tid;
            int r = f >> 5;               // k row 0..63
            int nc = (f & 31) * 4;        // n col 0..124
            int hn = nc >> 6;
            int kk = nc & 63;
            const float* src;
            if (mode == 0)
                src = W + (size_t)((n0 >> 6) + hn) * (D_ * DK_) + (size_t)(k0 + r) * DK_ + kk;
            else
                src = W + (size_t)(k0 + r) * D_ + n0 + nc;
            float4 a = *(const float4*)src;
            float h0 = __bfloat162float(__float2bfloat16_rn(a.x));
            float h1 = __bfloat162float(__float2bfloat16_rn(a.y));
            float h2 = __bfloat162float(__float2bfloat16_rn(a.z));
            float h3 = __bfloat162float(__float2bfloat16_rn(a.w));
            uint2 hp = make_uint2(pack_bf16(h0, h1), pack_bf16(h2, h3));
            uint2 lp = make_uint2(pack_bf16(a.x - h0, a.y - h1),
                                  pack_bf16(a.z - h2, a.w - h3));
            uint32_t off = (uint32_t)(hn * 8192 + r * 128 +
                                      (((kk >> 3) ^ (r & 7)) << 4) + ((kk & 4) << 1));
            *(uint2*)(smem + G_WHI + off) = hp;
            *(uint2*)(smem + G_WLO + off) = lp;
        }
        __syncthreads();

        // ---- compute ----
        const uint32_t wbase_h = sb + G_WHI + wn * 8192;
        const uint32_t wbase_l = sb + G_WLO + wn * 8192;
        #pragma unroll
        for (int g = 0; g < 4; g++) {
            uint32_t afh[2][4], afl[2][4];
            #pragma unroll
            for (int mt = 0; mt < 2; mt++) {
                int ra = 32 * wm + 16 * mt + ra_sub;
                int ch = 2 * g + cha_sub;
                uint32_t aoff = (uint32_t)(ra * 128 + ((ch ^ (ra & 7)) << 4));
                ldsm4(afh[mt], sb + G_AHI + aoff);
                ldsm4(afl[mt], sb + G_ALO + aoff);
            }
            #pragma unroll
            for (int tp = 0; tp < 4; tp++) {
                uint32_t bh[4], bl[4];
                int rb = 16 * g + rb_sub;
                int ch = 2 * tp + chb_sub;
                uint32_t boff = (uint32_t)(rb * 128 + ((ch ^ (rb & 7)) << 4));
                ldsm4t(bh, wbase_h + boff);
                ldsm4t(bl, wbase_l + boff);
                #pragma unroll
                for (int mt = 0; mt < 2; mt++) {
                    mma_bf16(acc[mt][2 * tp], afh[mt], bh);
                    mma_bf16(acc[mt][2 * tp], afh[mt], bl);
                    mma_bf16(acc[mt][2 * tp], afl[mt], bh);
                    mma_bf16(acc[mt][2 * tp + 1], afh[mt], bh + 2);
                    mma_bf16(acc[mt][2 * tp + 1], afh[mt], bl + 2);
                    mma_bf16(acc[mt][2 * tp + 1], afl[mt], bh + 2);
                }
            }
        }
    }

    // ---- epilogue ----
    if (mode == 0) {
        __nv_bfloat16* hi_arr = (which == 0) ? g_q_hi : (which == 1) ? g_k_hi : g_v_hi;
        __nv_bfloat16* lo_arr = (which == 0) ? g_q_lo : (which == 1) ? g_k_lo : g_v_lo;
        const int hh = (n0 >> 6) + wn;
        #pragma unroll
        for (int mt = 0; mt < 2; mt++) {
            int m1 = m0 + 32 * wm + 16 * mt + (L >> 2);
            #pragma unroll
            for (int nt = 0; nt < 8; nt++) {
                int kk = nt * 8 + (L & 3) * 2;
                #pragma unroll
                for (int half = 0; half < 2; half++) {
                    int m = m1 + half * 8;
                    int b = m >> 11;
                    int s = m & (L_ - 1);
                    float c0 = acc[mt][nt][2 * half + 0];
                    float c1 = acc[mt][nt][2 * half + 1];
                    float h0 = __bfloat162float(__float2bfloat16_rn(c0));
                    float h1 = __bfloat162float(__float2bfloat16_rn(c1));
                    size_t eidx = (((size_t)(b * H_ + hh) * L_ + s) * DK_ + kk) >> 1;
                    ((uint32_t*)hi_arr)[eidx] = pack_bf16(h0, h1);
                    ((uint32_t*)lo_arr)[eidx] = pack_bf16(c0 - h0, c1 - h1);
                }
            }
        }
    } else {
        #pragma unroll
        for (int mt = 0; mt < 2; mt++) {
            int m1 = m0 + 32 * wm + 16 * mt + (L >> 2);
            #pragma unroll
            for (int nt = 0; nt < 8; nt++) {
                int n = n0 + wn * 64 + nt * 8 + (L & 3) * 2;
                float b0 = bias[n], b1 = bias[n + 1];
                #pragma unroll
                for (int half = 0; half < 2; half++) {
                    int m = m1 + half * 8;
                    float2 v = make_float2(acc[mt][nt][2 * half + 0] + b0,
                                           acc[mt][nt][2 * half + 1] + b1);
                    *(float2*)(Cout + (size_t)m * D_ + n) = v;
                }
            }
        }
    }
}

// ---------------------------------------------------------------------------
// Tensor-core flash attention via mma.sync (bf16 hi/lo, 3 products).
// ---------------------------------------------------------------------------
#define QT 128
#define CT 64
#define O_QHI 0
#define O_QLO 16384
#define O_KHI 32768
#define O_KLO 40960
#define O_VHI 49152
#define O_VLO 57344
#define ATTN_SMEM 65536

__global__ __launch_bounds__(256, 2) void attn_mma_kernel() {
    extern __shared__ char smem[];
    const uint32_t sb = smem_to_u32(smem);
    const int tid = threadIdx.x;
    const int w = tid >> 5;
    const int L = tid & 31;
    const int q0 = blockIdx.x * QT;
    const int h = blockIdx.y;
    const int b = blockIdx.z;
    const size_t bh = (size_t)(b * H_ + h);

    {
        const uint4* qh4 = (const uint4*)(g_q_hi + (bh * L_ + q0) * DK_);
        const uint4* ql4 = (const uint4*)(g_q_lo + (bh * L_ + q0) * DK_);
        #pragma unroll
        for (int i = 0; i < 4; i++) {
            int f = i * 256 + tid;
            int r = f >> 3, ch = f & 7;
            uint32_t off = (uint32_t)(r * 128 + ((ch ^ (r & 7)) << 4));
            *(uint4*)(smem + O_QHI + off) = qh4[f];
            *(uint4*)(smem + O_QLO + off) = ql4[f];
        }
    }

    const uint4* kh4 = (const uint4*)(g_k_hi + bh * L_ * DK_);
    const uint4* kl4 = (const uint4*)(g_k_lo + bh * L_ * DK_);
    const uint4* vh4 = (const uint4*)(g_v_hi + bh * L_ * DK_);
    const uint4* vl4 = (const uint4*)(g_v_lo + bh * L_ * DK_);

    const int rq = 16 * w + (L & 7) + ((L >> 3) & 1) * 8;
    const int rk_sub = ((L >> 4) & 1) * 8 + (L & 7);
    const int rv_sub = ((L >> 3) & 1) * 8 + (L & 7);
    const int chq_sub = (L >> 4) & 1;
    const int chk_sub = (L >> 3) & 1;
    const int chv_sub = (L >> 4) & 1;

    const int r1 = 16 * w + (L >> 2);
    const unsigned* mp1 = g_mask + (size_t)(b * L_ + q0 + r1) * (L_ / 32);
    const unsigned* mp2 = mp1 + 8 * (L_ / 32);

    float o[8][4];
    #pragma unroll
    for (int t = 0; t < 8; t++)
        #pragma unroll
        for (int e = 0; e < 4; e++) o[t][e] = 0.f;
    float rs1 = 0.f, rs2 = 0.f;

    for (int c0 = 0; c0 < L_; c0 += CT) {
        __syncthreads();
        #pragma unroll
        for (int i = 0; i < 2; i++) {
            int f = i * 256 + tid;
            int r = f >> 3, ch = f & 7;
            uint32_t off = (uint32_t)(r * 128 + ((ch ^ (r & 7)) << 4));
            int gi = c0 * 8 + f;
            *(uint4*)(smem + O_KHI + off) = kh4[gi];
            *(uint4*)(smem + O_KLO + off) = kl4[gi];
            *(uint4*)(smem + O_VHI + off) = vh4[gi];
            *(uint4*)(smem + O_VLO + off) = vl4[gi];
        }
        __syncthreads();

        float s[8][4];
        #pragma unroll
        for (int t = 0; t < 8; t++)
            #pragma unroll
            for (int e = 0; e < 4; e++) s[t][e] = 0.f;

        #pragma unroll
        for (int g = 0; g < 4; g++) {
            uint32_t qh[4], ql[4];
            int chq = 2 * g + chq_sub;
            uint32_t qoff = (uint32_t)(rq * 128 + ((chq ^ (rq & 7)) << 4));
            ldsm4(qh, sb + O_QHI + qoff);
            ldsm4(ql, sb + O_QLO + qoff);
            #pragma unroll
            for (int tp = 0; tp < 4; tp++) {
                uint32_t kh[4], kl[4];
                int rk = 16 * tp + rk_sub;
                int chk = 2 * g + chk_sub;
                uint32_t koff = (uint32_t)(rk * 128 + ((chk ^ (rk & 7)) << 4));
                ldsm4(kh, sb + O_KHI + koff);
                ldsm4(kl, sb + O_KLO + koff);
                mma_bf16(s[2 * tp], qh, kh);
                mma_bf16(s[2 * tp], qh, kl);
                mma_bf16(s[2 * tp], ql, kh);
                mma_bf16(s[2 * tp + 1], qh, kh + 2);
                mma_bf16(s[2 * tp + 1], qh, kl + 2);
                mma_bf16(s[2 * tp + 1], ql, kh + 2);
            }
        }

        uint2 mwa = *(const uint2*)(mp1 + (c0 >> 5));
        uint2 mwb = *(const uint2*)(mp2 + (c0 >> 5));
        uint32_t ahi[4][4], alo[4][4];
        #pragma unroll
        for (int t = 0; t < 8; t++) {
            unsigned wa = (t < 4) ? mwa.x : mwa.y;
            unsigned wb = (t < 4) ? mwb.x : mwb.y;
            int sh = ((t & 3) << 3) + ((L & 3) << 1);
            float p0 = ((wa >> sh) & 1u)       ? __expf(s[t][0] * 0.125f) : 0.f;
            float p1 = ((wa >> (sh + 1)) & 1u) ? __expf(s[t][1] * 0.125f) : 0.f;
            float p2 = ((wb >> sh) & 1u)       ? __expf(s[t][2] * 0.125f) : 0.f;
            float p3 = ((wb >> (sh + 1)) & 1u) ? __expf(s[t][3] * 0.125f) : 0.f;
            rs1 += p0 + p1;
            rs2 += p2 + p3;
            float h0 = __bfloat162float(__float2bfloat16_rn(p0));
            float h1 = __bfloat162float(__float2bfloat16_rn(p1));
            float h2 = __bfloat162float(__float2bfloat16_rn(p2));
            float h3 = __bfloat162float(__float2bfloat16_rn(p3));
            int g = t >> 1, e = (t & 1) * 2;
            ahi[g][e]     = pack_bf16(h0, h1);
            ahi[g][e + 1] = pack_bf16(h2, h3);
            alo[g][e]     = pack_bf16(p0 - h0, p1 - h1);
            alo[g][e + 1] = pack_bf16(p2 - h2, p3 - h3);
        }

        #pragma unroll
        for (int g = 0; g < 4; g++) {
            int rv = 16 * g + rv_sub;
            #pragma unroll
            for (int tp = 0; tp < 4; tp++) {
                uint32_t vh[4], vl[4];
                int chv = 2 * tp + chv_sub;
                uint32_t voff = (uint32_t)(rv * 128 + ((chv ^ (rv & 7)) << 4));
                ldsm4t(vh, sb + O_VHI + voff);
                ldsm4t(vl, sb + O_VLO + voff);
                mma_bf16(o[2 * tp], ahi[g], vh);
                mma_bf16(o[2 * tp], ahi[g], vl);
                mma_bf16(o[2 * tp], alo[g], vh);
                mma_bf16(o[2 * tp + 1], ahi[g], vh + 2);
                mma_bf16(o[2 * tp + 1], ahi[g], vl + 2);
                mma_bf16(o[2 * tp + 1], alo[g], vh + 2);
            }
        }
    }

    rs1 += __shfl_xor_sync(0xffffffffu, rs1, 1);
    rs1 += __shfl_xor_sync(0xffffffffu, rs1, 2);
    rs2 += __shfl_xor_sync(0xffffffffu, rs2, 1);
    rs2 += __shfl_xor_sync(0xffffffffu, rs2, 2);
    float i1 = 1.f / rs1;
    float i2 = 1.f / rs2;

    float* op1 = g_mo + (size_t)(b * L_ + q0 + r1) * D_ + h * DK_;
    float* op2 = op1 + 8 * D_;
    #pragma unroll
    for (int t = 0; t < 8; t++) {
        int j = 8 * t + ((L & 3) << 1);
        float2 v1 = make_float2(o[t][0] * i1, o[t][1] * i1);
        float2 v2 = make_float2(o[t][2] * i2, o[t][3] * i2);
        *(float2*)(op1 + j) = v1;
        *(float2*)(op2 + j) = v2;
    }
}

// ---------------------------------------------------------------------------
extern "C" void kernel_launch(void* const* d_in, const int* in_sizes, int n_in,
                              void* d_out, int out_size) {
    const float* q   = (const float*)d_in[0];
    const float* k   = (const float*)d_in[1];
    const float* v   = (const float*)d_in[2];
    const int*   msk = (const int*)d_in[3];
    const float* Wq  = (const float*)d_in[4];
    const float* Wk  = (const float*)d_in[5];
    const float* Wv  = (const float*)d_in[6];
    const float* Wo  = (const float*)d_in[7];
    const float* bo  = (const float*)d_in[8];
    float* out = (float*)d_out;

    // Idempotent, non-captured API calls — safe to issue on every invocation.
    cudaFuncSetAttribute(attn_mma_kernel,
                         cudaFuncAttributeMaxDynamicSharedMemorySize, ATTN_SMEM);
    cudaFuncSetAttribute(gemm_tc_kernel,
                         cudaFuncAttributeMaxDynamicSharedMemorySize, GEMM_SMEM);

    pack_mask_kernel<<<(B_ * L_ * L_) / 256, 256>>>(msk);

    dim3 gg(D_ / 128, (B_ * L_) / 128);
    gemm_tc_kernel<<<gg, 256, GEMM_SMEM>>>(q, Wq, nullptr, nullptr, 0, 0);
    gemm_tc_kernel<<<gg, 256, GEMM_SMEM>>>(k, Wk, nullptr, nullptr, 0, 1);
    gemm_tc_kernel<<<gg, 256, GEMM_SMEM>>>(v, Wv, nullptr, nullptr, 0, 2);

    attn_mma_kernel<<<dim3(L_ / QT, H_, B_), 256, ATTN_SMEM>>>();

    gemm_tc_kernel<<<gg, 256, GEMM_SMEM>>>(nullptr, Wo, bo, out, 1, 0);
}

// round 8
// speedup vs baseline: 4.6141x; 1.1471x over previous
#include <cuda_runtime.h>
#include <cuda_bf16.h>
#include <math.h>
#include <cstdint>

#define B_ 4
#define L_ 2048
#define D_ 1024
#define H_ 16
#define DK_ 64

// ---------------------------------------------------------------------------
// Device scratch
// ---------------------------------------------------------------------------
__device__ unsigned g_mask[B_*L_*(L_/32)];   // 2 MB bit-packed mask
// pre-split bf16 hi/lo copies of GEMM operands
__device__ __nv_bfloat16 g_in_hi[3u*B_*L_*D_];   // q,k,v inputs [sel][m][d]
__device__ __nv_bfloat16 g_in_lo[3u*B_*L_*D_];
__device__ __nv_bfloat16 g_w_hi[4u*D_*D_];       // Wq,Wk,Wv (head-wise), Wo (row-major)
__device__ __nv_bfloat16 g_w_lo[4u*D_*D_];
__device__ __nv_bfloat16 g_mo_hi[B_*L_*D_];      // attention out hi/lo [m][d]
__device__ __nv_bfloat16 g_mo_lo[B_*L_*D_];
// attention operands produced by projection GEMMs, layout [b,h,s,k]
__device__ __nv_bfloat16 g_q_hi[B_*H_*L_*DK_];
__device__ __nv_bfloat16 g_q_lo[B_*H_*L_*DK_];
__device__ __nv_bfloat16 g_k_hi[B_*H_*L_*DK_];
__device__ __nv_bfloat16 g_k_lo[B_*H_*L_*DK_];
__device__ __nv_bfloat16 g_v_hi[B_*H_*L_*DK_];
__device__ __nv_bfloat16 g_v_lo[B_*H_*L_*DK_];

// ---------------------------------------------------------------------------
// primitives
// ---------------------------------------------------------------------------
__device__ __forceinline__ uint32_t smem_to_u32(const void* p) {
    uint32_t a;
    asm("{ .reg .u64 t; cvta.to.shared.u64 t, %1; cvt.u32.u64 %0, t; }" : "=r"(a) : "l"(p));
    return a;
}
__device__ __forceinline__ void ldsm4(uint32_t d[4], uint32_t addr) {
    asm volatile("ldmatrix.sync.aligned.m8n8.x4.shared.b16 {%0,%1,%2,%3}, [%4];"
        : "=r"(d[0]), "=r"(d[1]), "=r"(d[2]), "=r"(d[3]) : "r"(addr));
}
__device__ __forceinline__ void ldsm4t(uint32_t d[4], uint32_t addr) {
    asm volatile("ldmatrix.sync.aligned.m8n8.x4.trans.shared.b16 {%0,%1,%2,%3}, [%4];"
        : "=r"(d[0]), "=r"(d[1]), "=r"(d[2]), "=r"(d[3]) : "r"(addr));
}
__device__ __forceinline__ void mma_bf16(float c[4], const uint32_t a[4], const uint32_t b[2]) {
    asm volatile("mma.sync.aligned.m16n8k16.row.col.f32.bf16.bf16.f32 "
        "{%0,%1,%2,%3}, {%4,%5,%6,%7}, {%8,%9}, {%0,%1,%2,%3};"
        : "+f"(c[0]), "+f"(c[1]), "+f"(c[2]), "+f"(c[3])
        : "r"(a[0]), "r"(a[1]), "r"(a[2]), "r"(a[3]), "r"(b[0]), "r"(b[1]));
}
__device__ __forceinline__ uint32_t pack_bf16(float x, float y) {
    __nv_bfloat162 t = __floats2bfloat162_rn(x, y);
    return *reinterpret_cast<uint32_t*>(&t);
}
__device__ __forceinline__ void cp16(uint32_t dst, const void* src) {
    asm volatile("cp.async.cg.shared.global [%0], [%1], 16;" :: "r"(dst), "l"(src) : "memory");
}
#define CP_COMMIT() asm volatile("cp.async.commit_group;" ::: "memory")
#define CP_WAIT1()  asm volatile("cp.async.wait_group 1;" ::: "memory")
#define CP_WAIT0()  asm volatile("cp.async.wait_group 0;" ::: "memory")

// ---------------------------------------------------------------------------
// Mask bit-pack
// ---------------------------------------------------------------------------
__global__ void pack_mask_kernel(const int* __restrict__ mask) {
    int idx = blockIdx.x * blockDim.x + threadIdx.x;
    int v = mask[idx];
    unsigned bits = __ballot_sync(0xffffffffu, v != 0);
    if ((threadIdx.x & 31) == 0) g_mask[idx >> 5] = bits;
}

// ---------------------------------------------------------------------------
// fp32 -> bf16 hi/lo pre-split. dst_sel 0..2 = g_in + sel*8M, 3..6 = g_w + (sel-3)*1M
// ---------------------------------------------------------------------------
__global__ void conv_kernel(const float4* __restrict__ src, int dst_sel, int n4) {
    int i = blockIdx.x * blockDim.x + threadIdx.x;
    if (i >= n4) return;
    uint2* hi;
    uint2* lo;
    if (dst_sel < 3) {
        hi = (uint2*)(g_in_hi + (size_t)dst_sel * (B_*L_*D_));
        lo = (uint2*)(g_in_lo + (size_t)dst_sel * (B_*L_*D_));
    } else {
        hi = (uint2*)(g_w_hi + (size_t)(dst_sel - 3) * (D_*D_));
        lo = (uint2*)(g_w_lo + (size_t)(dst_sel - 3) * (D_*D_));
    }
    float4 a = src[i];
    float h0 = __bfloat162float(__float2bfloat16_rn(a.x));
    float h1 = __bfloat162float(__float2bfloat16_rn(a.y));
    float h2 = __bfloat162float(__float2bfloat16_rn(a.z));
    float h3 = __bfloat162float(__float2bfloat16_rn(a.w));
    hi[i] = make_uint2(pack_bf16(h0, h1), pack_bf16(h2, h3));
    lo[i] = make_uint2(pack_bf16(a.x - h0, a.y - h1), pack_bf16(a.z - h2, a.w - h3));
}

// ---------------------------------------------------------------------------
// Tensor-core GEMM, cp.async 2-stage pipeline, bf16 hi/lo x3.
// BM=128 BN=128 BK=32 (x32 iters), 256 thr (8 warps: 4m x 2n).
// A tiles from g_in (a_sel 0..2) or g_mo (a_sel 3); W from g_w[which].
// mode 0: scatter -> g_{q,k,v}_{hi,lo} [b,h,s,k]; mode 1: fp32 + bias -> Cout.
// Smem 64KB: A hi/lo [128][128B] (both stages packed in chunk dim),
//            W hi/lo [2 hn][2 p][32 kr][128B].
// ---------------------------------------------------------------------------
#define G_AHI 0
#define G_ALO 16384
#define G_WHI 32768
#define G_WLO 49152
#define GEMM_SMEM 65536

__global__ __launch_bounds__(256, 2) void gemm_tc_kernel(
    const float* __restrict__ bias,
    float* __restrict__ Cout,
    int a_sel, int which, int mode)
{
    extern __shared__ char smem[];
    const uint32_t sb = smem_to_u32(smem);
    const int tid = threadIdx.x;
    const int w = tid >> 5;
    const int L = tid & 31;
    const int wm = w >> 1;
    const int wn = w & 1;
    const int m0 = blockIdx.y * 128;
    const int n0 = blockIdx.x * 128;

    const __nv_bfloat16* a_hi = (a_sel < 3) ? g_in_hi + (size_t)a_sel * (B_*L_*D_) : g_mo_hi;
    const __nv_bfloat16* a_lo = (a_sel < 3) ? g_in_lo + (size_t)a_sel * (B_*L_*D_) : g_mo_lo;
    const __nv_bfloat16* w_hi = g_w_hi + (size_t)which * (D_*D_);
    const __nv_bfloat16* w_lo = g_w_lo + (size_t)which * (D_*D_);

    // lane-fixed fragment address components
    const int ra_sub = (L & 7) + ((L >> 3) & 1) * 8;
    const int cha_sub = (L >> 4) & 1;
    const int rb_sub = ((L >> 3) & 1) * 8 + (L & 7);
    const int chb_sub = (L >> 4) & 1;

    // staging indices (fixed per thread)
    const int a_r0 = tid >> 2;            // +64 for second
    const int a_c = tid & 3;
    const int w_kr = (tid >> 3) & 31;     // f = i*256+tid: hn = bit8
    const int w_c = tid & 7;

    float acc[2][8][4];
    #pragma unroll
    for (int mt = 0; mt < 2; mt++)
        #pragma unroll
        for (int nt = 0; nt < 8; nt++)
            #pragma unroll
            for (int e = 0; e < 4; e++) acc[mt][nt][e] = 0.f;

    auto stage = [&](int p, int k0) {
        // A: 128 rows x 32 k (4 chunks) hi+lo
        #pragma unroll
        for (int i = 0; i < 2; i++) {
            int r = a_r0 + i * 64;
            size_t so = (size_t)(m0 + r) * D_ + k0 + a_c * 8;
            uint32_t doff = (uint32_t)(r * 128 + (((4 * p + a_c) ^ (r & 7)) << 4));
            cp16(sb + G_AHI + doff, a_hi + so);
            cp16(sb + G_ALO + doff, a_lo + so);
        }
        // W: 2 hn x 32 kr x 8 n-chunks hi+lo
        #pragma unroll
        for (int i = 0; i < 2; i++) {
            int hn = i;   // tid covers 256 of 512; i = hn bit
            size_t so;
            if (mode == 0)
                so = (size_t)(2 * blockIdx.x + hn) * (D_ * DK_) + (size_t)(k0 + w_kr) * DK_ + w_c * 8;
            else
                so = (size_t)(k0 + w_kr) * D_ + n0 + hn * 64 + w_c * 8;
            uint32_t doff = (uint32_t)(hn * 8192 + p * 4096 + w_kr * 128 + ((w_c ^ (w_kr & 7)) << 4));
            cp16(sb + G_WHI + doff, w_hi + so);
            cp16(sb + G_WLO + doff, w_lo + so);
        }
        CP_COMMIT();
    };

    stage(0, 0);

    const uint32_t wb_h = sb + G_WHI + wn * 8192;
    const uint32_t wb_l = sb + G_WLO + wn * 8192;

    #pragma unroll 1
    for (int it = 0; it < 32; it++) {
        int p = it & 1;
        if (it + 1 < 32) {
            stage(p ^ 1, (it + 1) * 32);
            CP_WAIT1();
        } else {
            CP_WAIT0();
        }
        __syncthreads();

        #pragma unroll
        for (int g = 0; g < 2; g++) {
            uint32_t afh[2][4], afl[2][4];
            #pragma unroll
            for (int mt = 0; mt < 2; mt++) {
                int ra = 32 * wm + 16 * mt + ra_sub;
                int ch = 4 * p + 2 * g + cha_sub;
                uint32_t aoff = (uint32_t)(ra * 128 + ((ch ^ (ra & 7)) << 4));
                ldsm4(afh[mt], sb + G_AHI + aoff);
                ldsm4(afl[mt], sb + G_ALO + aoff);
            }
            #pragma unroll
            for (int tp = 0; tp < 4; tp++) {
                uint32_t bh[4], bl[4];
                int rb = 16 * g + rb_sub;
                int ch = 2 * tp + chb_sub;
                uint32_t boff = (uint32_t)(p * 4096 + rb * 128 + ((ch ^ (rb & 7)) << 4));
                ldsm4t(bh, wb_h + boff);
                ldsm4t(bl, wb_l + boff);
                #pragma unroll
                for (int mt = 0; mt < 2; mt++) {
                    mma_bf16(acc[mt][2 * tp], afh[mt], bh);
                    mma_bf16(acc[mt][2 * tp], afh[mt], bl);
                    mma_bf16(acc[mt][2 * tp], afl[mt], bh);
                    mma_bf16(acc[mt][2 * tp + 1], afh[mt], bh + 2);
                    mma_bf16(acc[mt][2 * tp + 1], afh[mt], bl + 2);
                    mma_bf16(acc[mt][2 * tp + 1], afl[mt], bh + 2);
                }
            }
        }
        __syncthreads();
    }

    // ---- epilogue ----
    if (mode == 0) {
        __nv_bfloat16* hi_arr = (which == 0) ? g_q_hi : (which == 1) ? g_k_hi : g_v_hi;
        __nv_bfloat16* lo_arr = (which == 0) ? g_q_lo : (which == 1) ? g_k_lo : g_v_lo;
        const int hh = 2 * blockIdx.x + wn;
        #pragma unroll
        for (int mt = 0; mt < 2; mt++) {
            int m1 = m0 + 32 * wm + 16 * mt + (L >> 2);
            #pragma unroll
            for (int nt = 0; nt < 8; nt++) {
                int kk = nt * 8 + (L & 3) * 2;
                #pragma unroll
                for (int half = 0; half < 2; half++) {
                    int m = m1 + half * 8;
                    int b = m >> 11;
                    int s = m & (L_ - 1);
                    float c0 = acc[mt][nt][2 * half + 0];
                    float c1 = acc[mt][nt][2 * half + 1];
                    float h0 = __bfloat162float(__float2bfloat16_rn(c0));
                    float h1 = __bfloat162float(__float2bfloat16_rn(c1));
                    size_t eidx = (((size_t)(b * H_ + hh) * L_ + s) * DK_ + kk) >> 1;
                    ((uint32_t*)hi_arr)[eidx] = pack_bf16(h0, h1);
                    ((uint32_t*)lo_arr)[eidx] = pack_bf16(c0 - h0, c1 - h1);
                }
            }
        }
    } else {
        #pragma unroll
        for (int mt = 0; mt < 2; mt++) {
            int m1 = m0 + 32 * wm + 16 * mt + (L >> 2);
            #pragma unroll
            for (int nt = 0; nt < 8; nt++) {
                int n = n0 + wn * 64 + nt * 8 + (L & 3) * 2;
                float b0 = bias[n], b1 = bias[n + 1];
                #pragma unroll
                for (int half = 0; half < 2; half++) {
                    int m = m1 + half * 8;
                    float2 v = make_float2(acc[mt][nt][2 * half + 0] + b0,
                                           acc[mt][nt][2 * half + 1] + b1);
                    *(float2*)(Cout + (size_t)m * D_ + n) = v;
                }
            }
        }
    }
}

// ---------------------------------------------------------------------------
// Tensor-core flash attention, cp.async 2-stage K/V pipeline.
// Smem 96KB: Q hi/lo 32KB + 2 stages x (K hi/lo + V hi/lo) 32KB each.
// ---------------------------------------------------------------------------
#define QT 128
#define CT 64
#define O_QHI 0
#define O_QLO 16384
#define O_STG 32768          /* + p*32768: KHI 0 / KLO 8192 / VHI 16384 / VLO 24576 */
#define ATTN_SMEM 98304

__global__ __launch_bounds__(256, 2) void attn_mma_kernel() {
    extern __shared__ char smem[];
    const uint32_t sb = smem_to_u32(smem);
    const int tid = threadIdx.x;
    const int w = tid >> 5;
    const int L = tid & 31;
    const int q0 = blockIdx.x * QT;
    const int h = blockIdx.y;
    const int b = blockIdx.z;
    const size_t bh = (size_t)(b * H_ + h);

    // stage Q (hi+lo) via plain stores (one-time)
    {
        const uint4* qh4 = (const uint4*)(g_q_hi + (bh * L_ + q0) * DK_);
        const uint4* ql4 = (const uint4*)(g_q_lo + (bh * L_ + q0) * DK_);
        #pragma unroll
        for (int i = 0; i < 4; i++) {
            int f = i * 256 + tid;
            int r = f >> 3, ch = f & 7;
            uint32_t off = (uint32_t)(r * 128 + ((ch ^ (r & 7)) << 4));
            *(uint4*)(smem + O_QHI + off) = qh4[f];
            *(uint4*)(smem + O_QLO + off) = ql4[f];
        }
    }

    const __nv_bfloat16* kh = g_k_hi + bh * L_ * DK_;
    const __nv_bfloat16* kl = g_k_lo + bh * L_ * DK_;
    const __nv_bfloat16* vh = g_v_hi + bh * L_ * DK_;
    const __nv_bfloat16* vl = g_v_lo + bh * L_ * DK_;

    const int kv_r0 = tid >> 3;        // +32 for second pass
    const int kv_c = tid & 7;

    auto load_kv = [&](int p, int c0) {
        uint32_t base = sb + O_STG + p * 32768;
        #pragma unroll
        for (int i = 0; i < 2; i++) {
            int r = kv_r0 + i * 32;
            size_t so = (size_t)(c0 + r) * DK_ + kv_c * 8;
            uint32_t doff = (uint32_t)(r * 128 + ((kv_c ^ (r & 7)) << 4));
            cp16(base + doff, kh + so);
            cp16(base + 8192 + doff, kl + so);
            cp16(base + 16384 + doff, vh + so);
            cp16(base + 24576 + doff, vl + so);
        }
        CP_COMMIT();
    };

    const int rq = 16 * w + (L & 7) + ((L >> 3) & 1) * 8;
    const int rk_sub = ((L >> 4) & 1) * 8 + (L & 7);
    const int rv_sub = ((L >> 3) & 1) * 8 + (L & 7);
    const int chq_sub = (L >> 4) & 1;
    const int chk_sub = (L >> 3) & 1;
    const int chv_sub = (L >> 4) & 1;

    const int r1 = 16 * w + (L >> 2);
    const unsigned* mp1 = g_mask + (size_t)(b * L_ + q0 + r1) * (L_ / 32);
    const unsigned* mp2 = mp1 + 8 * (L_ / 32);

    float o[8][4];
    #pragma unroll
    for (int t = 0; t < 8; t++)
        #pragma unroll
        for (int e = 0; e < 4; e++) o[t][e] = 0.f;
    float rs1 = 0.f, rs2 = 0.f;

    load_kv(0, 0);

    #pragma unroll 1
    for (int it = 0; it < L_ / CT; it++) {
        int p = it & 1;
        int c0 = it * CT;
        if (it + 1 < L_ / CT) {
            load_kv(p ^ 1, c0 + CT);
            CP_WAIT1();
        } else {
            CP_WAIT0();
        }
        __syncthreads();

        const uint32_t kb_h = sb + O_STG + p * 32768;
        const uint32_t kb_l = kb_h + 8192;
        const uint32_t vb_h = kb_h + 16384;
        const uint32_t vb_l = kb_h + 24576;

        float s[8][4];
        #pragma unroll
        for (int t = 0; t < 8; t++)
            #pragma unroll
            for (int e = 0; e < 4; e++) s[t][e] = 0.f;

        #pragma unroll
        for (int g = 0; g < 4; g++) {
            uint32_t qh_[4], ql_[4];
            int chq = 2 * g + chq_sub;
            uint32_t qoff = (uint32_t)(rq * 128 + ((chq ^ (rq & 7)) << 4));
            ldsm4(qh_, sb + O_QHI + qoff);
            ldsm4(ql_, sb + O_QLO + qoff);
            #pragma unroll
            for (int tp = 0; tp < 4; tp++) {
                uint32_t kh_[4], kl_[4];
                int rk = 16 * tp + rk_sub;
                int chk = 2 * g + chk_sub;
                uint32_t koff = (uint32_t)(rk * 128 + ((chk ^ (rk & 7)) << 4));
                ldsm4(kh_, kb_h + koff);
                ldsm4(kl_, kb_l + koff);
                mma_bf16(s[2 * tp], qh_, kh_);
                mma_bf16(s[2 * tp], qh_, kl_);
                mma_bf16(s[2 * tp], ql_, kh_);
                mma_bf16(s[2 * tp + 1], qh_, kh_ + 2);
                mma_bf16(s[2 * tp + 1], qh_, kl_ + 2);
                mma_bf16(s[2 * tp + 1], ql_, kh_ + 2);
            }
        }

        uint2 mwa = *(const uint2*)(mp1 + (c0 >> 5));
        uint2 mwb = *(const uint2*)(mp2 + (c0 >> 5));
        uint32_t ahi[4][4], alo[4][4];
        #pragma unroll
        for (int t = 0; t < 8; t++) {
            unsigned wa = (t < 4) ? mwa.x : mwa.y;
            unsigned wb = (t < 4) ? mwb.x : mwb.y;
            int sh = ((t & 3) << 3) + ((L & 3) << 1);
            float p0 = ((wa >> sh) & 1u)       ? __expf(s[t][0] * 0.125f) : 0.f;
            float p1 = ((wa >> (sh + 1)) & 1u) ? __expf(s[t][1] * 0.125f) : 0.f;
            float p2 = ((wb >> sh) & 1u)       ? __expf(s[t][2] * 0.125f) : 0.f;
            float p3 = ((wb >> (sh + 1)) & 1u) ? __expf(s[t][3] * 0.125f) : 0.f;
            rs1 += p0 + p1;
            rs2 += p2 + p3;
            float h0 = __bfloat162float(__float2bfloat16_rn(p0));
            float h1 = __bfloat162float(__float2bfloat16_rn(p1));
            float h2 = __bfloat162float(__float2bfloat16_rn(p2));
            float h3 = __bfloat162float(__float2bfloat16_rn(p3));
            int g = t >> 1, e = (t & 1) * 2;
            ahi[g][e]     = pack_bf16(h0, h1);
            ahi[g][e + 1] = pack_bf16(h2, h3);
            alo[g][e]     = pack_bf16(p0 - h0, p1 - h1);
            alo[g][e + 1] = pack_bf16(p2 - h2, p3 - h3);
        }

        #pragma unroll
        for (int g = 0; g < 4; g++) {
            int rv = 16 * g + rv_sub;
            #pragma unroll
            for (int tp = 0; tp < 4; tp++) {
                uint32_t vh_[4], vl_[4];
                int chv = 2 * tp + chv_sub;
                uint32_t voff = (uint32_t)(rv * 128 + ((chv ^ (rv & 7)) << 4));
                ldsm4t(vh_, vb_h + voff);
                ldsm4t(vl_, vb_l + voff);
                mma_bf16(o[2 * tp], ahi[g], vh_);
                mma_bf16(o[2 * tp], ahi[g], vl_);
                mma_bf16(o[2 * tp], alo[g], vh_);
                mma_bf16(o[2 * tp + 1], ahi[g], vh_ + 2);
                mma_bf16(o[2 * tp + 1], ahi[g], vl_ + 2);
                mma_bf16(o[2 * tp + 1], alo[g], vh_ + 2);
            }
        }
        __syncthreads();
    }

    rs1 += __shfl_xor_sync(0xffffffffu, rs1, 1);
    rs1 += __shfl_xor_sync(0xffffffffu, rs1, 2);
    rs2 += __shfl_xor_sync(0xffffffffu, rs2, 1);
    rs2 += __shfl_xor_sync(0xffffffffu, rs2, 2);
    float i1 = 1.f / rs1;
    float i2 = 1.f / rs2;

    // write g_mo as bf16 hi/lo (consumed directly by output GEMM)
    size_t row1 = (size_t)(b * L_ + q0 + r1) * D_ + h * DK_;
    size_t row2 = row1 + 8 * D_;
    #pragma unroll
    for (int t = 0; t < 8; t++) {
        int j = 8 * t + ((L & 3) << 1);
        float v0 = o[t][0] * i1, v1 = o[t][1] * i1;
        float v2 = o[t][2] * i2, v3 = o[t][3] * i2;
        float h0 = __bfloat162float(__float2bfloat16_rn(v0));
        float h1 = __bfloat162float(__float2bfloat16_rn(v1));
        float h2 = __bfloat162float(__float2bfloat16_rn(v2));
        float h3 = __bfloat162float(__float2bfloat16_rn(v3));
        ((uint32_t*)g_mo_hi)[(row1 + j) >> 1] = pack_bf16(h0, h1);
        ((uint32_t*)g_mo_lo)[(row1 + j) >> 1] = pack_bf16(v0 - h0, v1 - h1);
        ((uint32_t*)g_mo_hi)[(row2 + j) >> 1] = pack_bf16(h2, h3);
        ((uint32_t*)g_mo_lo)[(row2 + j) >> 1] = pack_bf16(v2 - h2, v3 - h3);
    }
}

// ---------------------------------------------------------------------------
extern "C" void kernel_launch(void* const* d_in, const int* in_sizes, int n_in,
                              void* d_out, int out_size) {
    const float* q   = (const float*)d_in[0];
    const float* k   = (const float*)d_in[1];
    const float* v   = (const float*)d_in[2];
    const int*   msk = (const int*)d_in[3];
    const float* Wq  = (const float*)d_in[4];
    const float* Wk  = (const float*)d_in[5];
    const float* Wv  = (const float*)d_in[6];
    const float* Wo  = (const float*)d_in[7];
    const float* bo  = (const float*)d_in[8];
    float* out = (float*)d_out;

    cudaFuncSetAttribute(attn_mma_kernel,
                         cudaFuncAttributeMaxDynamicSharedMemorySize, ATTN_SMEM);
    cudaFuncSetAttribute(gemm_tc_kernel,
                         cudaFuncAttributeMaxDynamicSharedMemorySize, GEMM_SMEM);

    pack_mask_kernel<<<(B_ * L_ * L_) / 256, 256>>>(msk);

    const int n4_in = (B_ * L_ * D_) / 4;     // 2M float4
    const int n4_w  = (D_ * D_) / 4;          // 256K float4
    conv_kernel<<<n4_in / 256, 256>>>((const float4*)q, 0, n4_in);
    conv_kernel<<<n4_in / 256, 256>>>((const float4*)k, 1, n4_in);
    conv_kernel<<<n4_in / 256, 256>>>((const float4*)v, 2, n4_in);
    conv_kernel<<<n4_w / 256, 256>>>((const float4*)Wq, 3, n4_w);
    conv_kernel<<<n4_w / 256, 256>>>((const float4*)Wk, 4, n4_w);
    conv_kernel<<<n4_w / 256, 256>>>((const float4*)Wv, 5, n4_w);
    conv_kernel<<<n4_w / 256, 256>>>((const float4*)Wo, 6, n4_w);

    dim3 gg(D_ / 128, (B_ * L_) / 128);
    gemm_tc_kernel<<<gg, 256, GEMM_SMEM>>>(nullptr, nullptr, 0, 0, 0);
    gemm_tc_kernel<<<gg, 256, GEMM_SMEM>>>(nullptr, nullptr, 1, 1, 0);
    gemm_tc_kernel<<<gg, 256, GEMM_SMEM>>>(nullptr, nullptr, 2, 2, 0);

    attn_mma_kernel<<<dim3(L_ / QT, H_, B_), 256, ATTN_SMEM>>>();

    gemm_tc_kernel<<<gg, 256, GEMM_SMEM>>>(bo, out, 3, 3, 1);
}

// round 9
// speedup vs baseline: 4.7616x; 1.0320x over previous
#include <cuda_runtime.h>
#include <cuda_bf16.h>
#include <math.h>
#include <cstdint>

#define B_ 4
#define L_ 2048
#define D_ 1024
#define H_ 16
#define DK_ 64

// ---------------------------------------------------------------------------
// Device scratch
// ---------------------------------------------------------------------------
__device__ unsigned g_mask[B_*L_*(L_/32)];   // 2 MB bit-packed mask
__device__ __nv_bfloat16 g_in_hi[3u*B_*L_*D_];   // q,k,v inputs [sel][m][d]
__device__ __nv_bfloat16 g_in_lo[3u*B_*L_*D_];
__device__ __nv_bfloat16 g_w_hi[4u*D_*D_];       // Wq,Wk,Wv (head-wise), Wo (row-major)
__device__ __nv_bfloat16 g_w_lo[4u*D_*D_];
__device__ __nv_bfloat16 g_mo_hi[B_*L_*D_];      // attention out hi/lo [m][d]
__device__ __nv_bfloat16 g_mo_lo[B_*L_*D_];
__device__ __nv_bfloat16 g_q_hi[B_*H_*L_*DK_];   // [b,h,s,k]
__device__ __nv_bfloat16 g_q_lo[B_*H_*L_*DK_];
__device__ __nv_bfloat16 g_k_hi[B_*H_*L_*DK_];
__device__ __nv_bfloat16 g_k_lo[B_*H_*L_*DK_];
__device__ __nv_bfloat16 g_v_hi[B_*H_*L_*DK_];
__device__ __nv_bfloat16 g_v_lo[B_*H_*L_*DK_];

// ---------------------------------------------------------------------------
// primitives
// ---------------------------------------------------------------------------
__device__ __forceinline__ uint32_t smem_to_u32(const void* p) {
    uint32_t a;
    asm("{ .reg .u64 t; cvta.to.shared.u64 t, %1; cvt.u32.u64 %0, t; }" : "=r"(a) : "l"(p));
    return a;
}
__device__ __forceinline__ void ldsm4(uint32_t d[4], uint32_t addr) {
    asm volatile("ldmatrix.sync.aligned.m8n8.x4.shared.b16 {%0,%1,%2,%3}, [%4];"
        : "=r"(d[0]), "=r"(d[1]), "=r"(d[2]), "=r"(d[3]) : "r"(addr));
}
__device__ __forceinline__ void ldsm4t(uint32_t d[4], uint32_t addr) {
    asm volatile("ldmatrix.sync.aligned.m8n8.x4.trans.shared.b16 {%0,%1,%2,%3}, [%4];"
        : "=r"(d[0]), "=r"(d[1]), "=r"(d[2]), "=r"(d[3]) : "r"(addr));
}
__device__ __forceinline__ void mma_bf16(float c[4], const uint32_t a[4], const uint32_t b[2]) {
    asm volatile("mma.sync.aligned.m16n8k16.row.col.f32.bf16.bf16.f32 "
        "{%0,%1,%2,%3}, {%4,%5,%6,%7}, {%8,%9}, {%0,%1,%2,%3};"
        : "+f"(c[0]), "+f"(c[1]), "+f"(c[2]), "+f"(c[3])
        : "r"(a[0]), "r"(a[1]), "r"(a[2]), "r"(a[3]), "r"(b[0]), "r"(b[1]));
}
__device__ __forceinline__ uint32_t pack_bf16(float x, float y) {
    __nv_bfloat162 t = __floats2bfloat162_rn(x, y);
    return *reinterpret_cast<uint32_t*>(&t);
}
__device__ __forceinline__ void cp16(uint32_t dst, const void* src) {
    asm volatile("cp.async.cg.shared.global [%0], [%1], 16;" :: "r"(dst), "l"(src) : "memory");
}
#define CP_COMMIT() asm volatile("cp.async.commit_group;" ::: "memory")
#define CP_WAIT1()  asm volatile("cp.async.wait_group 1;" ::: "memory")
#define CP_WAIT0()  asm volatile("cp.async.wait_group 0;" ::: "memory")

// ---------------------------------------------------------------------------
// Mask bit-pack
// ---------------------------------------------------------------------------
__global__ void pack_mask_kernel(const int* __restrict__ mask) {
    int idx = blockIdx.x * blockDim.x + threadIdx.x;
    int v = mask[idx];
    unsigned bits = __ballot_sync(0xffffffffu, v != 0);
    if ((threadIdx.x & 31) == 0) g_mask[idx >> 5] = bits;
}

// ---------------------------------------------------------------------------
// fp32 -> bf16 hi/lo pre-split. is_w=0: grid.y in 0..2 -> g_in; is_w=1: 0..3 -> g_w
// ---------------------------------------------------------------------------
__global__ void conv_kernel(const float4* __restrict__ p0, const float4* __restrict__ p1,
                            const float4* __restrict__ p2, const float4* __restrict__ p3,
                            int is_w, int n4) {
    int sel = blockIdx.y;
    const float4* src = (sel == 0) ? p0 : (sel == 1) ? p1 : (sel == 2) ? p2 : p3;
    uint2* hi;
    uint2* lo;
    if (is_w) {
        hi = (uint2*)(g_w_hi + (size_t)sel * (D_*D_));
        lo = (uint2*)(g_w_lo + (size_t)sel * (D_*D_));
    } else {
        hi = (uint2*)(g_in_hi + (size_t)sel * (B_*L_*D_));
        lo = (uint2*)(g_in_lo + (size_t)sel * (B_*L_*D_));
    }
    int i = blockIdx.x * blockDim.x + threadIdx.x;
    if (i >= n4) return;
    float4 a = src[i];
    float h0 = __bfloat162float(__float2bfloat16_rn(a.x));
    float h1 = __bfloat162float(__float2bfloat16_rn(a.y));
    float h2 = __bfloat162float(__float2bfloat16_rn(a.z));
    float h3 = __bfloat162float(__float2bfloat16_rn(a.w));
    hi[i] = make_uint2(pack_bf16(h0, h1), pack_bf16(h2, h3));
    lo[i] = make_uint2(pack_bf16(a.x - h0, a.y - h1), pack_bf16(a.z - h2, a.w - h3));
}

// ---------------------------------------------------------------------------
// Tensor-core GEMM, 3-stage cp.async pipeline, ONE sync per K-iter.
// BM=128 BN=128 BK=32 (x32 iters), 256 thr (8 warps: 4m x 2n).
// Smem 96KB: A stages 3x16KB (hi chunks 0-3 / lo chunks 4-7 in one 128B row),
//            W stages 3x16KB (hi 8KB [hn][kr][128B] + lo 8KB).
// ---------------------------------------------------------------------------
#define O_GA 0
#define O_GW 49152
#define GEMM_SMEM 98304

__global__ __launch_bounds__(256, 2) void gemm_tc_kernel(
    const float* __restrict__ bias,
    float* __restrict__ Cout,
    int a_sel, int which, int mode)
{
    extern __shared__ char smem[];
    const uint32_t sb = smem_to_u32(smem);
    const int tid = threadIdx.x;
    const int w = tid >> 5;
    const int L = tid & 31;
    const int wm = w >> 1;
    const int wn = w & 1;
    const int m0 = blockIdx.y * 128;
    const int n0 = blockIdx.x * 128;

    const __nv_bfloat16* a_hi = (a_sel < 3) ? g_in_hi + (size_t)a_sel * (B_*L_*D_) : g_mo_hi;
    const __nv_bfloat16* a_lo = (a_sel < 3) ? g_in_lo + (size_t)a_sel * (B_*L_*D_) : g_mo_lo;
    const __nv_bfloat16* w_hi = g_w_hi + (size_t)which * (D_*D_);
    const __nv_bfloat16* w_lo = g_w_lo + (size_t)which * (D_*D_);

    const int ra_sub = (L & 7) + ((L >> 3) & 1) * 8;
    const int cha_sub = (L >> 4) & 1;
    const int rb_sub = ((L >> 3) & 1) * 8 + (L & 7);
    const int chb_sub = (L >> 4) & 1;

    const int a_r = tid >> 2;         // 0..63 (+64)
    const int a_c = tid & 3;          // hi k-chunk 0..3 (lo = +4)
    const int w_kr = (tid >> 3) & 31;
    const int w_c = tid & 7;

    float acc[2][8][4];
    #pragma unroll
    for (int mt = 0; mt < 2; mt++)
        #pragma unroll
        for (int nt = 0; nt < 8; nt++)
            #pragma unroll
            for (int e = 0; e < 4; e++) acc[mt][nt][e] = 0.f;

    auto stage = [&](int s, int k0) {
        uint32_t abase = sb + O_GA + s * 16384;
        #pragma unroll
        for (int i = 0; i < 2; i++) {
            int r = a_r + i * 64;
            size_t so = (size_t)(m0 + r) * D_ + k0 + a_c * 8;
            cp16(abase + (uint32_t)(r * 128 + (((a_c    ) ^ (r & 7)) << 4)), a_hi + so);
            cp16(abase + (uint32_t)(r * 128 + (((a_c + 4) ^ (r & 7)) << 4)), a_lo + so);
        }
        uint32_t wbase = sb + O_GW + s * 16384;
        #pragma unroll
        for (int hn = 0; hn < 2; hn++) {
            size_t so;
            if (mode == 0)
                so = (size_t)(2 * blockIdx.x + hn) * (D_ * DK_) + (size_t)(k0 + w_kr) * DK_ + w_c * 8;
            else
                so = (size_t)(k0 + w_kr) * D_ + n0 + hn * 64 + w_c * 8;
            uint32_t doff = (uint32_t)(hn * 4096 + w_kr * 128 + ((w_c ^ (w_kr & 7)) << 4));
            cp16(wbase + doff, w_hi + so);
            cp16(wbase + 8192 + doff, w_lo + so);
        }
        CP_COMMIT();
    };

    stage(0, 0);
    stage(1, 32);

    #pragma unroll 1
    for (int it = 0; it < 32; it++) {
        if (it < 31) { CP_WAIT1(); } else { CP_WAIT0(); }
        __syncthreads();
        if (it + 2 < 32) stage((it + 2) % 3, (it + 2) * 32);

        const int cs = it % 3;
        const uint32_t abase = sb + O_GA + cs * 16384;
        const uint32_t wb_h = sb + O_GW + cs * 16384 + wn * 4096;
        const uint32_t wb_l = wb_h + 8192;

        #pragma unroll
        for (int g = 0; g < 2; g++) {
            uint32_t afh[2][4], afl[2][4];
            #pragma unroll
            for (int mt = 0; mt < 2; mt++) {
                int ra = 32 * wm + 16 * mt + ra_sub;
                int idh = 2 * g + cha_sub;
                uint32_t rbase = abase + (uint32_t)(ra * 128);
                ldsm4(afh[mt], rbase + (uint32_t)(((idh    ) ^ (ra & 7)) << 4));
                ldsm4(afl[mt], rbase + (uint32_t)(((idh + 4) ^ (ra & 7)) << 4));
            }
            #pragma unroll
            for (int tp = 0; tp < 4; tp++) {
                uint32_t bh[4], bl[4];
                int rb = 16 * g + rb_sub;
                int ch = 2 * tp + chb_sub;
                uint32_t boff = (uint32_t)(rb * 128 + ((ch ^ (rb & 7)) << 4));
                ldsm4t(bh, wb_h + boff);
                ldsm4t(bl, wb_l + boff);
                #pragma unroll
                for (int mt = 0; mt < 2; mt++) {
                    // interleaved: alternate acc targets to break RAW chains
                    mma_bf16(acc[mt][2 * tp],     afh[mt], bh);
                    mma_bf16(acc[mt][2 * tp + 1], afh[mt], bh + 2);
                    mma_bf16(acc[mt][2 * tp],     afh[mt], bl);
                    mma_bf16(acc[mt][2 * tp + 1], afh[mt], bl + 2);
                    mma_bf16(acc[mt][2 * tp],     afl[mt], bh);
                    mma_bf16(acc[mt][2 * tp + 1], afl[mt], bh + 2);
                }
            }
        }
    }

    // ---- epilogue ----
    if (mode == 0) {
        __nv_bfloat16* hi_arr = (which == 0) ? g_q_hi : (which == 1) ? g_k_hi : g_v_hi;
        __nv_bfloat16* lo_arr = (which == 0) ? g_q_lo : (which == 1) ? g_k_lo : g_v_lo;
        const int hh = 2 * blockIdx.x + wn;
        #pragma unroll
        for (int mt = 0; mt < 2; mt++) {
            int m1 = m0 + 32 * wm + 16 * mt + (L >> 2);
            #pragma unroll
            for (int nt = 0; nt < 8; nt++) {
                int kk = nt * 8 + (L & 3) * 2;
                #pragma unroll
                for (int half = 0; half < 2; half++) {
                    int m = m1 + half * 8;
                    int b = m >> 11;
                    int s = m & (L_ - 1);
                    float c0 = acc[mt][nt][2 * half + 0];
                    float c1 = acc[mt][nt][2 * half + 1];
                    float h0 = __bfloat162float(__float2bfloat16_rn(c0));
                    float h1 = __bfloat162float(__float2bfloat16_rn(c1));
                    size_t eidx = (((size_t)(b * H_ + hh) * L_ + s) * DK_ + kk) >> 1;
                    ((uint32_t*)hi_arr)[eidx] = pack_bf16(h0, h1);
                    ((uint32_t*)lo_arr)[eidx] = pack_bf16(c0 - h0, c1 - h1);
                }
            }
        }
    } else {
        #pragma unroll
        for (int mt = 0; mt < 2; mt++) {
            int m1 = m0 + 32 * wm + 16 * mt + (L >> 2);
            #pragma unroll
            for (int nt = 0; nt < 8; nt++) {
                int n = n0 + wn * 64 + nt * 8 + (L & 3) * 2;
                float b0 = bias[n], b1 = bias[n + 1];
                #pragma unroll
                for (int half = 0; half < 2; half++) {
                    int m = m1 + half * 8;
                    float2 v = make_float2(acc[mt][nt][2 * half + 0] + b0,
                                           acc[mt][nt][2 * half + 1] + b1);
                    *(float2*)(Cout + (size_t)m * D_ + n) = v;
                }
            }
        }
    }
}

// ---------------------------------------------------------------------------
// Tensor-core flash attention, cp.async 2-stage K/V pipeline.
// ---------------------------------------------------------------------------
#define QT 128
#define CT 64
#define O_QHI 0
#define O_QLO 16384
#define O_STG 32768          /* + p*32768: KHI 0 / KLO 8192 / VHI 16384 / VLO 24576 */
#define ATTN_SMEM 98304

__global__ __launch_bounds__(256, 2) void attn_mma_kernel() {
    extern __shared__ char smem[];
    const uint32_t sb = smem_to_u32(smem);
    const int tid = threadIdx.x;
    const int w = tid >> 5;
    const int L = tid & 31;
    const int q0 = blockIdx.x * QT;
    const int h = blockIdx.y;
    const int b = blockIdx.z;
    const size_t bh = (size_t)(b * H_ + h);

    {
        const uint4* qh4 = (const uint4*)(g_q_hi + (bh * L_ + q0) * DK_);
        const uint4* ql4 = (const uint4*)(g_q_lo + (bh * L_ + q0) * DK_);
        #pragma unroll
        for (int i = 0; i < 4; i++) {
            int f = i * 256 + tid;
            int r = f >> 3, ch = f & 7;
            uint32_t off = (uint32_t)(r * 128 + ((ch ^ (r & 7)) << 4));
            *(uint4*)(smem + O_QHI + off) = qh4[f];
            *(uint4*)(smem + O_QLO + off) = ql4[f];
        }
    }

    const __nv_bfloat16* kh = g_k_hi + bh * L_ * DK_;
    const __nv_bfloat16* kl = g_k_lo + bh * L_ * DK_;
    const __nv_bfloat16* vh = g_v_hi + bh * L_ * DK_;
    const __nv_bfloat16* vl = g_v_lo + bh * L_ * DK_;

    const int kv_r0 = tid >> 3;
    const int kv_c = tid & 7;

    auto load_kv = [&](int p, int c0) {
        uint32_t base = sb + O_STG + p * 32768;
        #pragma unroll
        for (int i = 0; i < 2; i++) {
            int r = kv_r0 + i * 32;
            size_t so = (size_t)(c0 + r) * DK_ + kv_c * 8;
            uint32_t doff = (uint32_t)(r * 128 + ((kv_c ^ (r & 7)) << 4));
            cp16(base + doff, kh + so);
            cp16(base + 8192 + doff, kl + so);
            cp16(base + 16384 + doff, vh + so);
            cp16(base + 24576 + doff, vl + so);
        }
        CP_COMMIT();
    };

    const int rq = 16 * w + (L & 7) + ((L >> 3) & 1) * 8;
    const int rk_sub = ((L >> 4) & 1) * 8 + (L & 7);
    const int rv_sub = ((L >> 3) & 1) * 8 + (L & 7);
    const int chq_sub = (L >> 4) & 1;
    const int chk_sub = (L >> 3) & 1;
    const int chv_sub = (L >> 4) & 1;

    const int r1 = 16 * w + (L >> 2);
    const unsigned* mp1 = g_mask + (size_t)(b * L_ + q0 + r1) * (L_ / 32);
    const unsigned* mp2 = mp1 + 8 * (L_ / 32);

    float o[8][4];
    #pragma unroll
    for (int t = 0; t < 8; t++)
        #pragma unroll
        for (int e = 0; e < 4; e++) o[t][e] = 0.f;
    float rs1 = 0.f, rs2 = 0.f;

    load_kv(0, 0);

    #pragma unroll 1
    for (int it = 0; it < L_ / CT; it++) {
        int p = it & 1;
        int c0 = it * CT;
        if (it + 1 < L_ / CT) {
            load_kv(p ^ 1, c0 + CT);
            CP_WAIT1();
        } else {
            CP_WAIT0();
        }
        __syncthreads();

        const uint32_t kb_h = sb + O_STG + p * 32768;
        const uint32_t kb_l = kb_h + 8192;
        const uint32_t vb_h = kb_h + 16384;
        const uint32_t vb_l = kb_h + 24576;

        float s[8][4];
        #pragma unroll
        for (int t = 0; t < 8; t++)
            #pragma unroll
            for (int e = 0; e < 4; e++) s[t][e] = 0.f;

        #pragma unroll
        for (int g = 0; g < 4; g++) {
            uint32_t qh_[4], ql_[4];
            int chq = 2 * g + chq_sub;
            uint32_t qoff = (uint32_t)(rq * 128 + ((chq ^ (rq & 7)) << 4));
            ldsm4(qh_, sb + O_QHI + qoff);
            ldsm4(ql_, sb + O_QLO + qoff);
            #pragma unroll
            for (int tp = 0; tp < 4; tp++) {
                uint32_t kh_[4], kl_[4];
                int rk = 16 * tp + rk_sub;
                int chk = 2 * g + chk_sub;
                uint32_t koff = (uint32_t)(rk * 128 + ((chk ^ (rk & 7)) << 4));
                ldsm4(kh_, kb_h + koff);
                ldsm4(kl_, kb_l + koff);
                mma_bf16(s[2 * tp],     qh_, kh_);
                mma_bf16(s[2 * tp + 1], qh_, kh_ + 2);
                mma_bf16(s[2 * tp],     qh_, kl_);
                mma_bf16(s[2 * tp + 1], qh_, kl_ + 2);
                mma_bf16(s[2 * tp],     ql_, kh_);
                mma_bf16(s[2 * tp + 1], ql_, kh_ + 2);
            }
        }

        uint2 mwa = *(const uint2*)(mp1 + (c0 >> 5));
        uint2 mwb = *(const uint2*)(mp2 + (c0 >> 5));
        uint32_t ahi[4][4], alo[4][4];
        #pragma unroll
        for (int t = 0; t < 8; t++) {
            unsigned wa = (t < 4) ? mwa.x : mwa.y;
            unsigned wb = (t < 4) ? mwb.x : mwb.y;
            int sh = ((t & 3) << 3) + ((L & 3) << 1);
            float p0 = ((wa >> sh) & 1u)       ? __expf(s[t][0] * 0.125f) : 0.f;
            float p1 = ((wa >> (sh + 1)) & 1u) ? __expf(s[t][1] * 0.125f) : 0.f;
            float p2 = ((wb >> sh) & 1u)       ? __expf(s[t][2] * 0.125f) : 0.f;
            float p3 = ((wb >> (sh + 1)) & 1u) ? __expf(s[t][3] * 0.125f) : 0.f;
            rs1 += p0 + p1;
            rs2 += p2 + p3;
            float h0 = __bfloat162float(__float2bfloat16_rn(p0));
            float h1 = __bfloat162float(__float2bfloat16_rn(p1));
            float h2 = __bfloat162float(__float2bfloat16_rn(p2));
            float h3 = __bfloat162float(__float2bfloat16_rn(p3));
            int g = t >> 1, e = (t & 1) * 2;
            ahi[g][e]     = pack_bf16(h0, h1);
            ahi[g][e + 1] = pack_bf16(h2, h3);
            alo[g][e]     = pack_bf16(p0 - h0, p1 - h1);
            alo[g][e + 1] = pack_bf16(p2 - h2, p3 - h3);
        }

        #pragma unroll
        for (int g = 0; g < 4; g++) {
            int rv = 16 * g + rv_sub;
            #pragma unroll
            for (int tp = 0; tp < 4; tp++) {
                uint32_t vh_[4], vl_[4];
                int chv = 2 * tp + chv_sub;
                uint32_t voff = (uint32_t)(rv * 128 + ((chv ^ (rv & 7)) << 4));
                ldsm4t(vh_, vb_h + voff);
                ldsm4t(vl_, vb_l + voff);
                mma_bf16(o[2 * tp],     ahi[g], vh_);
                mma_bf16(o[2 * tp + 1], ahi[g], vh_ + 2);
                mma_bf16(o[2 * tp],     ahi[g], vl_);
                mma_bf16(o[2 * tp + 1], ahi[g], vl_ + 2);
                mma_bf16(o[2 * tp],     alo[g], vh_);
                mma_bf16(o[2 * tp + 1], alo[g], vh_ + 2);
            }
        }
        __syncthreads();
    }

    rs1 += __shfl_xor_sync(0xffffffffu, rs1, 1);
    rs1 += __shfl_xor_sync(0xffffffffu, rs1, 2);
    rs2 += __shfl_xor_sync(0xffffffffu, rs2, 1);
    rs2 += __shfl_xor_sync(0xffffffffu, rs2, 2);
    float i1 = 1.f / rs1;
    float i2 = 1.f / rs2;

    size_t row1 = (size_t)(b * L_ + q0 + r1) * D_ + h * DK_;
    size_t row2 = row1 + 8 * D_;
    #pragma unroll
    for (int t = 0; t < 8; t++) {
        int j = 8 * t + ((L & 3) << 1);
        float v0 = o[t][0] * i1, v1 = o[t][1] * i1;
        float v2 = o[t][2] * i2, v3 = o[t][3] * i2;
        float h0 = __bfloat162float(__float2bfloat16_rn(v0));
        float h1 = __bfloat162float(__float2bfloat16_rn(v1));
        float h2 = __bfloat162float(__float2bfloat16_rn(v2));
        float h3 = __bfloat162float(__float2bfloat16_rn(v3));
        ((uint32_t*)g_mo_hi)[(row1 + j) >> 1] = pack_bf16(h0, h1);
        ((uint32_t*)g_mo_lo)[(row1 + j) >> 1] = pack_bf16(v0 - h0, v1 - h1);
        ((uint32_t*)g_mo_hi)[(row2 + j) >> 1] = pack_bf16(h2, h3);
        ((uint32_t*)g_mo_lo)[(row2 + j) >> 1] = pack_bf16(v2 - h2, v3 - h3);
    }
}

// ---------------------------------------------------------------------------
extern "C" void kernel_launch(void* const* d_in, const int* in_sizes, int n_in,
                              void* d_out, int out_size) {
    const float* q   = (const float*)d_in[0];
    const float* k   = (const float*)d_in[1];
    const float* v   = (const float*)d_in[2];
    const int*   msk = (const int*)d_in[3];
    const float* Wq  = (const float*)d_in[4];
    const float* Wk  = (const float*)d_in[5];
    const float* Wv  = (const float*)d_in[6];
    const float* Wo  = (const float*)d_in[7];
    const float* bo  = (const float*)d_in[8];
    float* out = (float*)d_out;

    cudaFuncSetAttribute(attn_mma_kernel,
                         cudaFuncAttributeMaxDynamicSharedMemorySize, ATTN_SMEM);
    cudaFuncSetAttribute(gemm_tc_kernel,
                         cudaFuncAttributeMaxDynamicSharedMemorySize, GEMM_SMEM);

    pack_mask_kernel<<<(B_ * L_ * L_) / 256, 256>>>(msk);

    const int n4_in = (B_ * L_ * D_) / 4;
    const int n4_w  = (D_ * D_) / 4;
    conv_kernel<<<dim3(n4_in / 256, 3), 256>>>((const float4*)q, (const float4*)k,
                                               (const float4*)v, nullptr, 0, n4_in);
    conv_kernel<<<dim3(n4_w / 256, 4), 256>>>((const float4*)Wq, (const float4*)Wk,
                                              (const float4*)Wv, (const float4*)Wo, 1, n4_w);

    dim3 gg(D_ / 128, (B_ * L_) / 128);
    gemm_tc_kernel<<<gg, 256, GEMM_SMEM>>>(nullptr, nullptr, 0, 0, 0);
    gemm_tc_kernel<<<gg, 256, GEMM_SMEM>>>(nullptr, nullptr, 1, 1, 0);
    gemm_tc_kernel<<<gg, 256, GEMM_SMEM>>>(nullptr, nullptr, 2, 2, 0);

    attn_mma_kernel<<<dim3(L_ / QT, H_, B_), 256, ATTN_SMEM>>>();

    gemm_tc_kernel<<<gg, 256, GEMM_SMEM>>>(bo, out, 3, 3, 1);
}

// round 10
// speedup vs baseline: 4.8812x; 1.0251x over previous
#include <cuda_runtime.h>
#include <cuda_bf16.h>
#include <math.h>
#include <cstdint>

#define B_ 4
#define L_ 2048
#define D_ 1024
#define H_ 16
#define DK_ 64

// ---------------------------------------------------------------------------
// Device scratch
// ---------------------------------------------------------------------------
__device__ unsigned g_mask[B_*L_*(L_/32)];   // 2 MB bit-packed mask
__device__ __nv_bfloat16 g_in_hi[3u*B_*L_*D_];   // q,k,v inputs [sel][m][d]
__device__ __nv_bfloat16 g_in_lo[3u*B_*L_*D_];
__device__ __nv_bfloat16 g_w_hi[4u*D_*D_];       // Wq,Wk,Wv (head-wise), Wo (row-major)
__device__ __nv_bfloat16 g_w_lo[4u*D_*D_];
__device__ __nv_bfloat16 g_mo_hi[B_*L_*D_];      // attention out hi/lo [m][d]
__device__ __nv_bfloat16 g_mo_lo[B_*L_*D_];
__device__ __nv_bfloat16 g_q_hi[B_*H_*L_*DK_];   // [b,h,s,k]
__device__ __nv_bfloat16 g_q_lo[B_*H_*L_*DK_];
__device__ __nv_bfloat16 g_k_hi[B_*H_*L_*DK_];
__device__ __nv_bfloat16 g_k_lo[B_*H_*L_*DK_];
__device__ __nv_bfloat16 g_v_hi[B_*H_*L_*DK_];
__device__ __nv_bfloat16 g_v_lo[B_*H_*L_*DK_];

// ---------------------------------------------------------------------------
// primitives
// ---------------------------------------------------------------------------
__device__ __forceinline__ uint32_t smem_to_u32(const void* p) {
    uint32_t a;
    asm("{ .reg .u64 t; cvta.to.shared.u64 t, %1; cvt.u32.u64 %0, t; }" : "=r"(a) : "l"(p));
    return a;
}
__device__ __forceinline__ void ldsm4(uint32_t d[4], uint32_t addr) {
    asm volatile("ldmatrix.sync.aligned.m8n8.x4.shared.b16 {%0,%1,%2,%3}, [%4];"
        : "=r"(d[0]), "=r"(d[1]), "=r"(d[2]), "=r"(d[3]) : "r"(addr));
}
__device__ __forceinline__ void ldsm4t(uint32_t d[4], uint32_t addr) {
    asm volatile("ldmatrix.sync.aligned.m8n8.x4.trans.shared.b16 {%0,%1,%2,%3}, [%4];"
        : "=r"(d[0]), "=r"(d[1]), "=r"(d[2]), "=r"(d[3]) : "r"(addr));
}
__device__ __forceinline__ void mma_bf16(float c[4], const uint32_t a[4], const uint32_t b[2]) {
    asm volatile("mma.sync.aligned.m16n8k16.row.col.f32.bf16.bf16.f32 "
        "{%0,%1,%2,%3}, {%4,%5,%6,%7}, {%8,%9}, {%0,%1,%2,%3};"
        : "+f"(c[0]), "+f"(c[1]), "+f"(c[2]), "+f"(c[3])
        : "r"(a[0]), "r"(a[1]), "r"(a[2]), "r"(a[3]), "r"(b[0]), "r"(b[1]));
}
__device__ __forceinline__ uint32_t pack_bf16(float x, float y) {
    __nv_bfloat162 t = __floats2bfloat162_rn(x, y);
    return *reinterpret_cast<uint32_t*>(&t);
}
__device__ __forceinline__ void cp16(uint32_t dst, const void* src) {
    asm volatile("cp.async.cg.shared.global [%0], [%1], 16;" :: "r"(dst), "l"(src) : "memory");
}
#define CP_COMMIT() asm volatile("cp.async.commit_group;" ::: "memory")
#define CP_WAIT1()  asm volatile("cp.async.wait_group 1;" ::: "memory")
#define CP_WAIT0()  asm volatile("cp.async.wait_group 0;" ::: "memory")

// ---------------------------------------------------------------------------
// Mask bit-pack
// ---------------------------------------------------------------------------
__global__ void pack_mask_kernel(const int* __restrict__ mask) {
    int idx = blockIdx.x * blockDim.x + threadIdx.x;
    int v = mask[idx];
    unsigned bits = __ballot_sync(0xffffffffu, v != 0);
    if ((threadIdx.x & 31) == 0) g_mask[idx >> 5] = bits;
}

// ---------------------------------------------------------------------------
// fp32 -> bf16 hi/lo pre-split. is_w=0: grid.y in 0..2 -> g_in; is_w=1: 0..3 -> g_w
// ---------------------------------------------------------------------------
__global__ void conv_kernel(const float4* __restrict__ p0, const float4* __restrict__ p1,
                            const float4* __restrict__ p2, const float4* __restrict__ p3,
                            int is_w, int n4) {
    int sel = blockIdx.y;
    const float4* src = (sel == 0) ? p0 : (sel == 1) ? p1 : (sel == 2) ? p2 : p3;
    uint2* hi;
    uint2* lo;
    if (is_w) {
        hi = (uint2*)(g_w_hi + (size_t)sel * (D_*D_));
        lo = (uint2*)(g_w_lo + (size_t)sel * (D_*D_));
    } else {
        hi = (uint2*)(g_in_hi + (size_t)sel * (B_*L_*D_));
        lo = (uint2*)(g_in_lo + (size_t)sel * (B_*L_*D_));
    }
    int i = blockIdx.x * blockDim.x + threadIdx.x;
    if (i >= n4) return;
    float4 a = src[i];
    float h0 = __bfloat162float(__float2bfloat16_rn(a.x));
    float h1 = __bfloat162float(__float2bfloat16_rn(a.y));
    float h2 = __bfloat162float(__float2bfloat16_rn(a.z));
    float h3 = __bfloat162float(__float2bfloat16_rn(a.w));
    hi[i] = make_uint2(pack_bf16(h0, h1), pack_bf16(h2, h3));
    lo[i] = make_uint2(pack_bf16(a.x - h0, a.y - h1), pack_bf16(a.z - h2, a.w - h3));
}

// ---------------------------------------------------------------------------
// Tensor-core GEMM, 3-stage cp.async pipeline, ONE sync per K-iter.
// BM=128 BN=128 BK=32 (x32 iters), 256 thr (8 warps: 4m x 2n).
// mode 0: merged projections — blockIdx.z = which in {0,1,2} (q,k,v).
// mode 1: output projection, A = g_mo hi/lo, +bias -> Cout fp32.
// ---------------------------------------------------------------------------
#define O_GA 0
#define O_GW 49152
#define GEMM_SMEM 98304

__global__ __launch_bounds__(256, 2) void gemm_tc_kernel(
    const float* __restrict__ bias,
    float* __restrict__ Cout,
    int mode)
{
    extern __shared__ char smem[];
    const uint32_t sb = smem_to_u32(smem);
    const int tid = threadIdx.x;
    const int w = tid >> 5;
    const int L = tid & 31;
    const int wm = w >> 1;
    const int wn = w & 1;
    const int m0 = blockIdx.y * 128;
    const int n0 = blockIdx.x * 128;
    const int which = (mode == 0) ? (int)blockIdx.z : 3;

    const __nv_bfloat16* a_hi = (mode == 0) ? g_in_hi + (size_t)which * (B_*L_*D_) : g_mo_hi;
    const __nv_bfloat16* a_lo = (mode == 0) ? g_in_lo + (size_t)which * (B_*L_*D_) : g_mo_lo;
    const __nv_bfloat16* w_hi = g_w_hi + (size_t)which * (D_*D_);
    const __nv_bfloat16* w_lo = g_w_lo + (size_t)which * (D_*D_);

    const int ra_sub = (L & 7) + ((L >> 3) & 1) * 8;
    const int cha_sub = (L >> 4) & 1;
    const int rb_sub = ((L >> 3) & 1) * 8 + (L & 7);
    const int chb_sub = (L >> 4) & 1;

    const int a_r = tid >> 2;
    const int a_c = tid & 3;
    const int w_kr = (tid >> 3) & 31;
    const int w_c = tid & 7;

    float acc[2][8][4];
    #pragma unroll
    for (int mt = 0; mt < 2; mt++)
        #pragma unroll
        for (int nt = 0; nt < 8; nt++)
            #pragma unroll
            for (int e = 0; e < 4; e++) acc[mt][nt][e] = 0.f;

    auto stage = [&](int s, int k0) {
        uint32_t abase = sb + O_GA + s * 16384;
        #pragma unroll
        for (int i = 0; i < 2; i++) {
            int r = a_r + i * 64;
            size_t so = (size_t)(m0 + r) * D_ + k0 + a_c * 8;
            cp16(abase + (uint32_t)(r * 128 + (((a_c    ) ^ (r & 7)) << 4)), a_hi + so);
            cp16(abase + (uint32_t)(r * 128 + (((a_c + 4) ^ (r & 7)) << 4)), a_lo + so);
        }
        uint32_t wbase = sb + O_GW + s * 16384;
        #pragma unroll
        for (int hn = 0; hn < 2; hn++) {
            size_t so;
            if (mode == 0)
                so = (size_t)(2 * blockIdx.x + hn) * (D_ * DK_) + (size_t)(k0 + w_kr) * DK_ + w_c * 8;
            else
                so = (size_t)(k0 + w_kr) * D_ + n0 + hn * 64 + w_c * 8;
            uint32_t doff = (uint32_t)(hn * 4096 + w_kr * 128 + ((w_c ^ (w_kr & 7)) << 4));
            cp16(wbase + doff, w_hi + so);
            cp16(wbase + 8192 + doff, w_lo + so);
        }
        CP_COMMIT();
    };

    stage(0, 0);
    stage(1, 32);

    #pragma unroll 1
    for (int it = 0; it < 32; it++) {
        if (it < 31) { CP_WAIT1(); } else { CP_WAIT0(); }
        __syncthreads();
        if (it + 2 < 32) stage((it + 2) % 3, (it + 2) * 32);

        const int cs = it % 3;
        const uint32_t abase = sb + O_GA + cs * 16384;
        const uint32_t wb_h = sb + O_GW + cs * 16384 + wn * 4096;
        const uint32_t wb_l = wb_h + 8192;

        #pragma unroll
        for (int g = 0; g < 2; g++) {
            uint32_t afh[2][4], afl[2][4];
            #pragma unroll
            for (int mt = 0; mt < 2; mt++) {
                int ra = 32 * wm + 16 * mt + ra_sub;
                int idh = 2 * g + cha_sub;
                uint32_t rbase = abase + (uint32_t)(ra * 128);
                ldsm4(afh[mt], rbase + (uint32_t)(((idh    ) ^ (ra & 7)) << 4));
                ldsm4(afl[mt], rbase + (uint32_t)(((idh + 4) ^ (ra & 7)) << 4));
            }
            #pragma unroll
            for (int tp = 0; tp < 4; tp++) {
                uint32_t bh[4], bl[4];
                int rb = 16 * g + rb_sub;
                int ch = 2 * tp + chb_sub;
                uint32_t boff = (uint32_t)(rb * 128 + ((ch ^ (rb & 7)) << 4));
                ldsm4t(bh, wb_h + boff);
                ldsm4t(bl, wb_l + boff);
                #pragma unroll
                for (int mt = 0; mt < 2; mt++) {
                    mma_bf16(acc[mt][2 * tp],     afh[mt], bh);
                    mma_bf16(acc[mt][2 * tp + 1], afh[mt], bh + 2);
                    mma_bf16(acc[mt][2 * tp],     afh[mt], bl);
                    mma_bf16(acc[mt][2 * tp + 1], afh[mt], bl + 2);
                    mma_bf16(acc[mt][2 * tp],     afl[mt], bh);
                    mma_bf16(acc[mt][2 * tp + 1], afl[mt], bh + 2);
                }
            }
        }
    }

    // ---- epilogue ----
    if (mode == 0) {
        __nv_bfloat16* hi_arr = (which == 0) ? g_q_hi : (which == 1) ? g_k_hi : g_v_hi;
        __nv_bfloat16* lo_arr = (which == 0) ? g_q_lo : (which == 1) ? g_k_lo : g_v_lo;
        const int hh = 2 * blockIdx.x + wn;
        #pragma unroll
        for (int mt = 0; mt < 2; mt++) {
            int m1 = m0 + 32 * wm + 16 * mt + (L >> 2);
            #pragma unroll
            for (int nt = 0; nt < 8; nt++) {
                int kk = nt * 8 + (L & 3) * 2;
                #pragma unroll
                for (int half = 0; half < 2; half++) {
                    int m = m1 + half * 8;
                    int b = m >> 11;
                    int s = m & (L_ - 1);
                    float c0 = acc[mt][nt][2 * half + 0];
                    float c1 = acc[mt][nt][2 * half + 1];
                    float h0 = __bfloat162float(__float2bfloat16_rn(c0));
                    float h1 = __bfloat162float(__float2bfloat16_rn(c1));
                    size_t eidx = (((size_t)(b * H_ + hh) * L_ + s) * DK_ + kk) >> 1;
                    ((uint32_t*)hi_arr)[eidx] = pack_bf16(h0, h1);
                    ((uint32_t*)lo_arr)[eidx] = pack_bf16(c0 - h0, c1 - h1);
                }
            }
        }
    } else {
        #pragma unroll
        for (int mt = 0; mt < 2; mt++) {
            int m1 = m0 + 32 * wm + 16 * mt + (L >> 2);
            #pragma unroll
            for (int nt = 0; nt < 8; nt++) {
                int n = n0 + wn * 64 + nt * 8 + (L & 3) * 2;
                float b0 = bias[n], b1 = bias[n + 1];
                #pragma unroll
                for (int half = 0; half < 2; half++) {
                    int m = m1 + half * 8;
                    float2 v = make_float2(acc[mt][nt][2 * half + 0] + b0,
                                           acc[mt][nt][2 * half + 1] + b1);
                    *(float2*)(Cout + (size_t)m * D_ + n) = v;
                }
            }
        }
    }
}

// ---------------------------------------------------------------------------
// Tensor-core flash attention, cp.async 2-stage K/V pipeline, ONE sync/iter:
//   per iter: wait_group 0 -> sync -> issue load(it+1) -> compute(stage p).
// Safety: a warp past iter-it's sync has finished iter-(it-1)'s compute, i.e.
// all reads of stage p^1 — so the post-sync load into p^1 is race-free.
// ---------------------------------------------------------------------------
#define QT 128
#define CT 64
#define O_QHI 0
#define O_QLO 16384
#define O_STG 32768          /* + p*32768: KHI 0 / KLO 8192 / VHI 16384 / VLO 24576 */
#define ATTN_SMEM 98304

__global__ __launch_bounds__(256, 2) void attn_mma_kernel() {
    extern __shared__ char smem[];
    const uint32_t sb = smem_to_u32(smem);
    const int tid = threadIdx.x;
    const int w = tid >> 5;
    const int L = tid & 31;
    const int q0 = blockIdx.x * QT;
    const int h = blockIdx.y;
    const int b = blockIdx.z;
    const size_t bh = (size_t)(b * H_ + h);

    {
        const uint4* qh4 = (const uint4*)(g_q_hi + (bh * L_ + q0) * DK_);
        const uint4* ql4 = (const uint4*)(g_q_lo + (bh * L_ + q0) * DK_);
        #pragma unroll
        for (int i = 0; i < 4; i++) {
            int f = i * 256 + tid;
            int r = f >> 3, ch = f & 7;
            uint32_t off = (uint32_t)(r * 128 + ((ch ^ (r & 7)) << 4));
            *(uint4*)(smem + O_QHI + off) = qh4[f];
            *(uint4*)(smem + O_QLO + off) = ql4[f];
        }
    }

    const __nv_bfloat16* kh = g_k_hi + bh * L_ * DK_;
    const __nv_bfloat16* kl = g_k_lo + bh * L_ * DK_;
    const __nv_bfloat16* vh = g_v_hi + bh * L_ * DK_;
    const __nv_bfloat16* vl = g_v_lo + bh * L_ * DK_;

    const int kv_r0 = tid >> 3;
    const int kv_c = tid & 7;

    auto load_kv = [&](int p, int c0) {
        uint32_t base = sb + O_STG + p * 32768;
        #pragma unroll
        for (int i = 0; i < 2; i++) {
            int r = kv_r0 + i * 32;
            size_t so = (size_t)(c0 + r) * DK_ + kv_c * 8;
            uint32_t doff = (uint32_t)(r * 128 + ((kv_c ^ (r & 7)) << 4));
            cp16(base + doff, kh + so);
            cp16(base + 8192 + doff, kl + so);
            cp16(base + 16384 + doff, vh + so);
            cp16(base + 24576 + doff, vl + so);
        }
        CP_COMMIT();
    };

    const int rq = 16 * w + (L & 7) + ((L >> 3) & 1) * 8;
    const int rk_sub = ((L >> 4) & 1) * 8 + (L & 7);
    const int rv_sub = ((L >> 3) & 1) * 8 + (L & 7);
    const int chq_sub = (L >> 4) & 1;
    const int chk_sub = (L >> 3) & 1;
    const int chv_sub = (L >> 4) & 1;

    const int r1 = 16 * w + (L >> 2);
    const unsigned* mp1 = g_mask + (size_t)(b * L_ + q0 + r1) * (L_ / 32);
    const unsigned* mp2 = mp1 + 8 * (L_ / 32);

    float o[8][4];
    #pragma unroll
    for (int t = 0; t < 8; t++)
        #pragma unroll
        for (int e = 0; e < 4; e++) o[t][e] = 0.f;
    float rs1 = 0.f, rs2 = 0.f;

    load_kv(0, 0);

    #pragma unroll 1
    for (int it = 0; it < L_ / CT; it++) {
        int p = it & 1;
        int c0 = it * CT;
        CP_WAIT0();
        __syncthreads();
        if (it + 1 < L_ / CT) load_kv(p ^ 1, c0 + CT);

        const uint32_t kb_h = sb + O_STG + p * 32768;
        const uint32_t kb_l = kb_h + 8192;
        const uint32_t vb_h = kb_h + 16384;
        const uint32_t vb_l = kb_h + 24576;

        float s[8][4];
        #pragma unroll
        for (int t = 0; t < 8; t++)
            #pragma unroll
            for (int e = 0; e < 4; e++) s[t][e] = 0.f;

        #pragma unroll
        for (int g = 0; g < 4; g++) {
            uint32_t qh_[4], ql_[4];
            int chq = 2 * g + chq_sub;
            uint32_t qoff = (uint32_t)(rq * 128 + ((chq ^ (rq & 7)) << 4));
            ldsm4(qh_, sb + O_QHI + qoff);
            ldsm4(ql_, sb + O_QLO + qoff);
            #pragma unroll
            for (int tp = 0; tp < 4; tp++) {
                uint32_t kh_[4], kl_[4];
                int rk = 16 * tp + rk_sub;
                int chk = 2 * g + chk_sub;
                uint32_t koff = (uint32_t)(rk * 128 + ((chk ^ (rk & 7)) << 4));
                ldsm4(kh_, kb_h + koff);
                ldsm4(kl_, kb_l + koff);
                mma_bf16(s[2 * tp],     qh_, kh_);
                mma_bf16(s[2 * tp + 1], qh_, kh_ + 2);
                mma_bf16(s[2 * tp],     qh_, kl_);
                mma_bf16(s[2 * tp + 1], qh_, kl_ + 2);
                mma_bf16(s[2 * tp],     ql_, kh_);
                mma_bf16(s[2 * tp + 1], ql_, kh_ + 2);
            }
        }

        uint2 mwa = *(const uint2*)(mp1 + (c0 >> 5));
        uint2 mwb = *(const uint2*)(mp2 + (c0 >> 5));
        uint32_t ahi[4][4], alo[4][4];
        #pragma unroll
        for (int t = 0; t < 8; t++) {
            unsigned wa = (t < 4) ? mwa.x : mwa.y;
            unsigned wb = (t < 4) ? mwb.x : mwb.y;
            int sh = ((t & 3) << 3) + ((L & 3) << 1);
            float p0 = ((wa >> sh) & 1u)       ? __expf(s[t][0] * 0.125f) : 0.f;
            float p1 = ((wa >> (sh + 1)) & 1u) ? __expf(s[t][1] * 0.125f) : 0.f;
            float p2 = ((wb >> sh) & 1u)       ? __expf(s[t][2] * 0.125f) : 0.f;
            float p3 = ((wb >> (sh + 1)) & 1u) ? __expf(s[t][3] * 0.125f) : 0.f;
            rs1 += p0 + p1;
            rs2 += p2 + p3;
            float h0 = __bfloat162float(__float2bfloat16_rn(p0));
            float h1 = __bfloat162float(__float2bfloat16_rn(p1));
            float h2 = __bfloat162float(__float2bfloat16_rn(p2));
            float h3 = __bfloat162float(__float2bfloat16_rn(p3));
            int g = t >> 1, e = (t & 1) * 2;
            ahi[g][e]     = pack_bf16(h0, h1);
            ahi[g][e + 1] = pack_bf16(h2, h3);
            alo[g][e]     = pack_bf16(p0 - h0, p1 - h1);
            alo[g][e + 1] = pack_bf16(p2 - h2, p3 - h3);
        }

        #pragma unroll
        for (int g = 0; g < 4; g++) {
            int rv = 16 * g + rv_sub;
            #pragma unroll
            for (int tp = 0; tp < 4; tp++) {
                uint32_t vh_[4], vl_[4];
                int chv = 2 * tp + chv_sub;
                uint32_t voff = (uint32_t)(rv * 128 + ((chv ^ (rv & 7)) << 4));
                ldsm4t(vh_, vb_h + voff);
                ldsm4t(vl_, vb_l + voff);
                mma_bf16(o[2 * tp],     ahi[g], vh_);
                mma_bf16(o[2 * tp + 1], ahi[g], vh_ + 2);
                mma_bf16(o[2 * tp],     ahi[g], vl_);
                mma_bf16(o[2 * tp + 1], ahi[g], vl_ + 2);
                mma_bf16(o[2 * tp],     alo[g], vh_);
                mma_bf16(o[2 * tp + 1], alo[g], vh_ + 2);
            }
        }
    }

    rs1 += __shfl_xor_sync(0xffffffffu, rs1, 1);
    rs1 += __shfl_xor_sync(0xffffffffu, rs1, 2);
    rs2 += __shfl_xor_sync(0xffffffffu, rs2, 1);
    rs2 += __shfl_xor_sync(0xffffffffu, rs2, 2);
    float i1 = 1.f / rs1;
    float i2 = 1.f / rs2;

    size_t row1 = (size_t)(b * L_ + q0 + r1) * D_ + h * DK_;
    size_t row2 = row1 + 8 * D_;
    #pragma unroll
    for (int t = 0; t < 8; t++) {
        int j = 8 * t + ((L & 3) << 1);
        float v0 = o[t][0] * i1, v1 = o[t][1] * i1;
        float v2 = o[t][2] * i2, v3 = o[t][3] * i2;
        float h0 = __bfloat162float(__float2bfloat16_rn(v0));
        float h1 = __bfloat162float(__float2bfloat16_rn(v1));
        float h2 = __bfloat162float(__float2bfloat16_rn(v2));
        float h3 = __bfloat162float(__float2bfloat16_rn(v3));
        ((uint32_t*)g_mo_hi)[(row1 + j) >> 1] = pack_bf16(h0, h1);
        ((uint32_t*)g_mo_lo)[(row1 + j) >> 1] = pack_bf16(v0 - h0, v1 - h1);
        ((uint32_t*)g_mo_hi)[(row2 + j) >> 1] = pack_bf16(h2, h3);
        ((uint32_t*)g_mo_lo)[(row2 + j) >> 1] = pack_bf16(v2 - h2, v3 - h3);
    }
}

// ---------------------------------------------------------------------------
extern "C" void kernel_launch(void* const* d_in, const int* in_sizes, int n_in,
                              void* d_out, int out_size) {
    const float* q   = (const float*)d_in[0];
    const float* k   = (const float*)d_in[1];
    const float* v   = (const float*)d_in[2];
    const int*   msk = (const int*)d_in[3];
    const float* Wq  = (const float*)d_in[4];
    const float* Wk  = (const float*)d_in[5];
    const float* Wv  = (const float*)d_in[6];
    const float* Wo  = (const float*)d_in[7];
    const float* bo  = (const float*)d_in[8];
    float* out = (float*)d_out;

    cudaFuncSetAttribute(attn_mma_kernel,
                         cudaFuncAttributeMaxDynamicSharedMemorySize, ATTN_SMEM);
    cudaFuncSetAttribute(gemm_tc_kernel,
                         cudaFuncAttributeMaxDynamicSharedMemorySize, GEMM_SMEM);

    pack_mask_kernel<<<(B_ * L_ * L_) / 256, 256>>>(msk);

    const int n4_in = (B_ * L_ * D_) / 4;
    const int n4_w  = (D_ * D_) / 4;
    conv_kernel<<<dim3(n4_in / 256, 3), 256>>>((const float4*)q, (const float4*)k,
                                               (const float4*)v, nullptr, 0, n4_in);
    conv_kernel<<<dim3(n4_w / 256, 4), 256>>>((const float4*)Wq, (const float4*)Wk,
                                              (const float4*)Wv, (const float4*)Wo, 1, n4_w);

    // merged q/k/v projections: one launch, blockIdx.z = which
    gemm_tc_kernel<<<dim3(D_ / 128, (B_ * L_) / 128, 3), 256, GEMM_SMEM>>>(nullptr, nullptr, 0);

    attn_mma_kernel<<<dim3(L_ / QT, H_, B_), 256, ATTN_SMEM>>>();

    gemm_tc_kernel<<<dim3(D_ / 128, (B_ * L_) / 128, 1), 256, GEMM_SMEM>>>(bo, out, 1);
}